// round 13
// baseline (speedup 1.0000x reference)
#include <cuda_runtime.h>
#include <math.h>
#include <math_constants.h>

#define B_   32
#define V_   2048
#define K_   40
#define KP1  41
#define FIN  64
#define D_   4
#define P_   64
#define FILT 128
#define N_   (B_ * V_)
#define QW   8          // queries per block (512 thr, 16 warps, 2 warps/query)
#define FULL 0xffffffffu

// ---- scratch (static device arrays: no allocation allowed) ----
__device__ float g_coords[N_ * 4];                  // 1 MB
__device__ float g_feats[(size_t)N_ * FIN];         // 16 MB
__device__ float g_coll[(size_t)N_ * 2 * P_];       // 32 MB

// ============================================================
// Kernel 1: coords = x@W_s + b_s ; feats = x@W_f + b_f
// ============================================================
__global__ void __launch_bounds__(256) k_transform(
    const float* __restrict__ x,
    const float* __restrict__ Ws, const float* __restrict__ bs,
    const float* __restrict__ Wf, const float* __restrict__ bf)
{
    __shared__ float xsT[64 * 65];
    __shared__ float wfs[64 * 64];
    __shared__ float wss[64 * 4];

    const int tid = threadIdx.x;
    const int r0 = blockIdx.x * 64;

    #pragma unroll
    for (int i = 0; i < 4; i++) {
        int f = tid + i * 256;
        reinterpret_cast<float4*>(wfs)[f] =
            reinterpret_cast<const float4*>(Wf)[f];
    }
    wss[tid] = Ws[tid];

    #pragma unroll
    for (int i = 0; i < 4; i++) {
        int f   = tid + i * 256;
        int row = f >> 4;
        int kq  = (f & 15) * 4;
        float4 v = *reinterpret_cast<const float4*>(
            x + (size_t)(r0 + row) * FIN + kq);
        xsT[(kq + 0) * 65 + row] = v.x;
        xsT[(kq + 1) * 65 + row] = v.y;
        xsT[(kq + 2) * 65 + row] = v.z;
        xsT[(kq + 3) * 65 + row] = v.w;
    }
    __syncthreads();

    const int tx = tid & 15, ty = tid >> 4;
    float acc[4][4];
    #pragma unroll
    for (int i = 0; i < 4; i++)
        #pragma unroll
        for (int j = 0; j < 4; j++) acc[i][j] = 0.f;

    #pragma unroll 16
    for (int k = 0; k < 64; k++) {
        float a0 = xsT[k * 65 + ty * 4 + 0];
        float a1 = xsT[k * 65 + ty * 4 + 1];
        float a2 = xsT[k * 65 + ty * 4 + 2];
        float a3 = xsT[k * 65 + ty * 4 + 3];
        float4 b = *reinterpret_cast<const float4*>(&wfs[k * 64 + tx * 4]);
        acc[0][0] = fmaf(a0, b.x, acc[0][0]); acc[0][1] = fmaf(a0, b.y, acc[0][1]);
        acc[0][2] = fmaf(a0, b.z, acc[0][2]); acc[0][3] = fmaf(a0, b.w, acc[0][3]);
        acc[1][0] = fmaf(a1, b.x, acc[1][0]); acc[1][1] = fmaf(a1, b.y, acc[1][1]);
        acc[1][2] = fmaf(a1, b.z, acc[1][2]); acc[1][3] = fmaf(a1, b.w, acc[1][3]);
        acc[2][0] = fmaf(a2, b.x, acc[2][0]); acc[2][1] = fmaf(a2, b.y, acc[2][1]);
        acc[2][2] = fmaf(a2, b.z, acc[2][2]); acc[2][3] = fmaf(a2, b.w, acc[2][3]);
        acc[3][0] = fmaf(a3, b.x, acc[3][0]); acc[3][1] = fmaf(a3, b.y, acc[3][1]);
        acc[3][2] = fmaf(a3, b.z, acc[3][2]); acc[3][3] = fmaf(a3, b.w, acc[3][3]);
    }

    float4 bfv = *reinterpret_cast<const float4*>(bf + tx * 4);
    #pragma unroll
    for (int i = 0; i < 4; i++) {
        int row = r0 + ty * 4 + i;
        float4 o;
        o.x = acc[i][0] + bfv.x; o.y = acc[i][1] + bfv.y;
        o.z = acc[i][2] + bfv.z; o.w = acc[i][3] + bfv.w;
        *reinterpret_cast<float4*>(g_feats + (size_t)row * FIN + tx * 4) = o;
    }

    {
        int crow = tid >> 2, cc = tid & 3;
        float a2 = 0.f;
        #pragma unroll 16
        for (int k = 0; k < 64; k++)
            a2 = fmaf(xsT[k * 65 + crow], wss[k * 4 + cc], a2);
        g_coords[(r0 + crow) * 4 + cc] = a2 + bs[cc];
    }
}

// ============================================================
// helpers
// ============================================================
__device__ __forceinline__ unsigned keyof(float d2) {
    unsigned u = __float_as_uint(d2);
    u ^= (u & 0x80000000u) ? 0xFFFFFFFFu : 0x80000000u;
    return u;
}
__device__ __forceinline__ unsigned long long ullmin_(unsigned long long a, unsigned long long b) {
    return a < b ? a : b;
}
__device__ __forceinline__ float sqnorm(float4 c) {
    float s = c.x * c.x;
    s = fmaf(c.y, c.y, s); s = fmaf(c.z, c.z, s); s = fmaf(c.w, c.w, s);
    return s;
}
__device__ __forceinline__ unsigned long long shfl_xor_u64(unsigned long long v, int st) {
    unsigned lo = (unsigned)(v & 0xffffffffull);
    unsigned hi = (unsigned)(v >> 32);
    lo = __shfl_xor_sync(FULL, lo, st);
    hi = __shfl_xor_sync(FULL, hi, st);
    return ((unsigned long long)hi << 32) | (unsigned long long)lo;
}
__device__ __forceinline__ void bstep_u32(unsigned &v, int ebase, int sz, int st, int lane) {
    unsigned o = __shfl_xor_sync(FULL, v, st);
    bool up    = ((ebase & sz) == 0);
    bool lower = ((lane & st) == 0);
    unsigned mn = min(v, o), mx = max(v, o);
    v = (lower == up) ? mn : mx;
}
__device__ __forceinline__ void bstep_u64(unsigned long long &v, int ebase, int sz, int st, int lane) {
    unsigned long long o = shfl_xor_u64(v, st);
    bool up    = ((ebase & sz) == 0);
    bool lower = ((lane & st) == 0);
    unsigned long long mn = v < o ? v : o;
    unsigned long long mx = v < o ? o : v;
    v = (lower == up) ? mn : mx;
}
// ascending sort of 64 u32 (2 regs/lane, element e = r*32+lane)
__device__ __forceinline__ void sort64_u32(unsigned &s0, unsigned &s1, int lane) {
    #pragma unroll
    for (int sz = 2; sz <= 32; sz <<= 1) {
        #pragma unroll
        for (int st = sz >> 1; st >= 1; st >>= 1) {
            bstep_u32(s0, lane, sz, st, lane);
            bstep_u32(s1, 32 + lane, sz, st, lane);
        }
    }
    { unsigned mn = min(s0, s1), mx = max(s0, s1); s0 = mn; s1 = mx; }
    #pragma unroll
    for (int st = 16; st >= 1; st >>= 1) {
        bstep_u32(s0, lane, 64, st, lane);
        bstep_u32(s1, 32 + lane, 64, st, lane);
    }
}
// ascending sort of 64 u64 (2 regs/lane) — proven in R8
__device__ __forceinline__ void sort64_u64(unsigned long long &c0, unsigned long long &c1, int lane) {
    #pragma unroll
    for (int sz = 2; sz <= 32; sz <<= 1) {
        #pragma unroll
        for (int st = sz >> 1; st >= 1; st >>= 1) {
            bstep_u64(c0, lane, sz, st, lane);
            bstep_u64(c1, 32 + lane, sz, st, lane);
        }
    }
    { unsigned long long mn = c0 < c1 ? c0 : c1, mx = c0 < c1 ? c1 : c0; c0 = mn; c1 = mx; }
    #pragma unroll
    for (int st = 16; st >= 1; st >>= 1) {
        bstep_u64(c0, lane, 64, st, lane);
        bstep_u64(c1, 32 + lane, 64, st, lane);
    }
}

// key of candidate idx = t*32+lane (t in 0..63) — identical fmaf chain everywhere
__device__ __forceinline__ unsigned keyat(const float4* sc, const float* ssq,
                                          float4 qc, float qsq, int t, int lane) {
    int idx = t * 32 + lane;
    float4 c = sc[idx];
    float dot = qc.x * c.x;
    dot = fmaf(qc.y, c.y, dot);
    dot = fmaf(qc.z, c.z, dot);
    dot = fmaf(qc.w, c.w, dot);
    float d2 = qsq + ssq[idx] - 2.f * dot;
    return keyof(d2);
}

// (weight, feature-base offset) for neighbor idx — reference weight form
__device__ __forceinline__ float2 wfor(const float4* sc, float4 qc, int idx) {
    float4 c = sc[idx];
    float dx = qc.x - c.x, dy = qc.y - c.y, dz = qc.z - c.z, dw = qc.w - c.w;
    float dist = dx * dx;
    dist = fmaf(dy, dy, dist);
    dist = fmaf(dz, dz, dist);
    dist = fmaf(dw, dw, dist);
    float2 r;
    r.x = expf(-fabsf(dist * 10.f));
    r.y = __int_as_float(idx << 6);
    return r;
}

// ---- rare exact fallback (nc > 64): one warp, keys recomputed from smem ----
__device__ __noinline__ void fb_exact(
    const float4* sc, const float* ssq, float2* cf,
    float4 qc, float qsq, unsigned gmin, unsigned Bq, int lane)
{
    const unsigned lanemask_lt = (1u << lane) - 1u;
    unsigned lo = gmin, hi = Bq;
    unsigned T = 0; int cT = 0; bool exact = false;
    while (lo < hi) {
        unsigned mid = lo + ((hi - lo) >> 1);
        int c = 0;
        for (int t = 0; t < 64; t++)
            c += (keyat(sc, ssq, qc, qsq, t, lane) <= mid) ? 1 : 0;
        c = __reduce_add_sync(FULL, c);
        if (c == KP1) {
            unsigned mx = 0;
            for (int t = 0; t < 64; t++) {
                unsigned u = keyat(sc, ssq, qc, qsq, t, lane);
                if (u <= mid) mx = max(mx, u);
            }
            T = __reduce_max_sync(FULL, mx);
            cT = KP1; exact = true; break;
        }
        if (c > KP1) hi = mid; else lo = mid + 1;
    }
    if (!exact) {
        T = lo;
        int c = 0;
        for (int t = 0; t < 64; t++)
            c += (keyat(sc, ssq, qc, qsq, t, lane) <= T) ? 1 : 0;
        cT = __reduce_add_sync(FULL, c);
    }
    unsigned long long selmask = 0ull;
    if (cT == KP1) {
        for (int t = 0; t < 64; t++)
            if (keyat(sc, ssq, qc, qsq, t, lane) <= T) selmask |= (1ull << t);
    } else {
        int c_less = 0;
        for (int t = 0; t < 64; t++)
            c_less += (keyat(sc, ssq, qc, qsq, t, lane) < T) ? 1 : 0;
        c_less = __reduce_add_sync(FULL, c_less);
        const int take_eq = KP1 - c_less;
        int running = 0;
        for (int t = 0; t < 64; t++) {
            unsigned u = keyat(sc, ssq, qc, qsq, t, lane);
            bool eq = (u == T);
            unsigned bal = __ballot_sync(FULL, eq);
            bool sel = (u < T);
            if (eq) {
                int rank = running + __popc(bal & lanemask_lt);
                sel = sel || (rank < take_eq);
            }
            running += __popc(bal);
            if (sel) selmask |= (1ull << t);
        }
    }
    // drop = min composite among selected
    unsigned long long mymin = 0xFFFFFFFFFFFFFFFFull;
    {
        unsigned long long m = selmask;
        while (m) {
            int t = __ffsll((long long)m) - 1;
            m &= m - 1;
            unsigned u = keyat(sc, ssq, qc, qsq, t, lane);
            mymin = ullmin_(mymin, ((unsigned long long)u << 32) | (unsigned)(t * 32 + lane));
        }
    }
    #pragma unroll
    for (int o = 16; o; o >>= 1)
        mymin = ullmin_(mymin, shfl_xor_u64(mymin, o));
    const int dropidx = (int)(unsigned)(mymin & 0xffffffffull);
    if ((dropidx & 31) == lane)
        selmask &= ~(1ull << (dropidx >> 5));
    // scatter 40 (weight, off)
    int cnt = __popcll(selmask);
    int sc2 = cnt;
    #pragma unroll
    for (int o = 1; o < 32; o <<= 1) {
        int v = __shfl_up_sync(FULL, sc2, o);
        if (lane >= o) sc2 += v;
    }
    int p = sc2 - cnt;
    unsigned long long m = selmask;
    while (m) {
        int t = __ffsll((long long)m) - 1;
        m &= m - 1;
        if (p < K_) cf[p] = wfor(sc, qc, t * 32 + lane);
        p++;
    }
}

// ============================================================
// Kernel 2: exact KNN + pooling. 2 warps per query (32 key regs),
// shared candidate list + composite sort; feature-split pooling.
// ============================================================
__global__ void __launch_bounds__(512, 2) k_knn()
{
    __shared__ float4 sc[V_];                        // 32 KB
    __shared__ float  ssq[V_];                       // 8 KB
    __shared__ unsigned long long cand[QW][64];      // 4 KB
    __shared__ unsigned sB[QW][2];
    __shared__ unsigned sG[QW][2];
    __shared__ int s_cnt[QW];

    const int b   = blockIdx.y;
    const int tid = threadIdx.x;
    const float4* cg = reinterpret_cast<const float4*>(g_coords) + (size_t)b * V_;
    for (int t = tid; t < V_; t += 512) {
        float4 c = cg[t];
        sc[t]  = c;
        ssq[t] = sqnorm(c);
    }
    if (tid < QW) s_cnt[tid] = 0;
    __syncthreads();

    const int wid  = tid >> 5;
    const int lane = tid & 31;
    const int qq   = wid >> 1;          // query slot 0..7
    const int h    = wid & 1;           // half 0/1
    const int q    = blockIdx.x * QW + qq;
    const unsigned lanemask_lt = (1u << lane) - 1u;

    const float4 qc  = sc[q];
    const float  qsq = ssq[q];
    const int base_idx = h * 1024;

    // ---- distance keys for own half + per-lane min2 ----
    unsigned key[32];
    unsigned m1 = 0xFFFFFFFFu, m2 = 0xFFFFFFFFu;
    #pragma unroll
    for (int j = 0; j < 32; j++) {
        int idx = base_idx + j * 32 + lane;
        float4 c = sc[idx];
        float dot = qc.x * c.x;
        dot = fmaf(qc.y, c.y, dot);
        dot = fmaf(qc.z, c.z, dot);
        dot = fmaf(qc.w, c.w, dot);
        float d2 = qsq + ssq[idx] - 2.f * dot;
        unsigned u = keyof(d2);
        key[j] = u;
        unsigned nm1 = min(m1, u);
        unsigned nm2 = min(m2, max(m1, u));
        m1 = nm1; m2 = nm2;
    }

    // ---- per-half bound: 41st smallest of this half's min2 union ----
    {
        unsigned s0 = m1, s1 = m2;
        sort64_u32(s0, s1, lane);
        if (lane == 8) sB[qq][h] = s1;   // element 40
        if (lane == 0) sG[qq][h] = s0;   // element 0
    }
    __syncthreads();
    const unsigned Bq   = min(sB[qq][0], sB[qq][1]);   // count(<=Bq) >= 41 globally
    const unsigned gmin = min(sG[qq][0], sG[qq][1]);

    // ---- compact own half (key <= Bq) into shared candidate list ----
    {
        unsigned cm = 0;
        #pragma unroll
        for (int j = 0; j < 32; j++)
            if (key[j] <= Bq) cm |= (1u << j);
        int myc  = __popc(cm);
        int wtot = __reduce_add_sync(FULL, myc);
        int base = 0;
        if (lane == 0) base = atomicAdd(&s_cnt[qq], wtot);
        base = __shfl_sync(FULL, base, 0);
        int sc2 = myc;
        #pragma unroll
        for (int o = 1; o < 32; o <<= 1) {
            int v = __shfl_up_sync(FULL, sc2, o);
            if (lane >= o) sc2 += v;
        }
        int p = base + sc2 - myc;
        unsigned m = cm;
        while (m) {
            int j = __ffs(m) - 1;
            m &= m - 1;
            if (p < 64)
                cand[qq][p] = ((unsigned long long)key[j] << 32)
                            | (unsigned)(base_idx + j * 32 + lane);
            p++;
        }
    }
    __syncthreads();

    const int nc = s_cnt[qq];
    float2* cf = reinterpret_cast<float2*>(cand[qq]);

    // ---- fast path: composite sort; elems 1..40 = exact neighbor set ----
    if (nc <= 64 && h == 0) {
        const unsigned long long PADV = 0xFFFFFFFFFFFFFFFFull;
        unsigned long long c0 = (lane      < nc) ? cand[qq][lane]      : PADV;
        unsigned long long c1 = (32 + lane < nc) ? cand[qq][32 + lane] : PADV;
        sort64_u64(c0, c1, lane);
        int idx0 = (int)(unsigned)(c0 & 0xffffffffull);
        int idx1 = (int)(unsigned)(c1 & 0xffffffffull);
        __syncwarp();
        if (lane >= 1) cf[lane - 1]  = wfor(sc, qc, idx0);   // elems 1..31
        if (lane < 9)  cf[31 + lane] = wfor(sc, qc, idx1);   // elems 32..40
    }
    __syncthreads();

    // ---- rare exact fallback ----
    if (nc > 64 && h == 0)
        fb_exact(sc, ssq, cf, qc, qsq, gmin, Bq, lane);
    __syncthreads();

    // ---- pooling: warp pair splits features; lane owns feature f ----
    const float* fb = g_feats + (size_t)b * V_ * FIN;
    const int f = h * 32 + lane;
    float mx = -CUDART_INF_F, sm = 0.f;
    #pragma unroll 8
    for (int n = 0; n < K_; n++) {
        float2 iw = cf[n];
        int off = __float_as_int(iw.y);      // idx*64
        float v = fb[off + f] * iw.x;
        mx = fmaxf(mx, v);
        sm += v;
    }
    float* o = g_coll + (size_t)(b * V_ + q) * (2 * P_);
    o[f]      = mx;
    o[64 + f] = sm * (1.f / (float)K_);
}

// ============================================================
// Kernel 3: out = tanh([x | collected] @ W_out + b_out)
// (R9 known-good single-buffered version)
// ============================================================
__global__ void __launch_bounds__(256) k_out(
    const float* __restrict__ x,
    const float* __restrict__ Wout, const float* __restrict__ bout,
    float* __restrict__ out)
{
    __shared__ float As[16 * 132];
    __shared__ float Bs[16 * 128];

    const int tidx = threadIdx.x;
    const int tx = tidx & 15, ty = tidx >> 4;
    const int r0 = blockIdx.x * 128;

    float acc[8][8];
    #pragma unroll
    for (int i = 0; i < 8; i++)
        #pragma unroll
        for (int j = 0; j < 8; j++) acc[i][j] = 0.f;

    for (int kt = 0; kt < 12; kt++) {
        #pragma unroll
        for (int i = 0; i < 2; i++) {
            int t   = tidx + i * 256;
            int row = t >> 2;
            int kq  = (t & 3) * 4;
            int gk  = kt * 16 + kq;
            const float* src = (gk < FIN)
                ? (x      + (size_t)(r0 + row) * FIN  + gk)
                : (g_coll + (size_t)(r0 + row) * 128 + (gk - FIN));
            float4 v = *reinterpret_cast<const float4*>(src);
            As[(kq + 0) * 132 + row] = v.x;
            As[(kq + 1) * 132 + row] = v.y;
            As[(kq + 2) * 132 + row] = v.z;
            As[(kq + 3) * 132 + row] = v.w;
        }
        #pragma unroll
        for (int i = 0; i < 2; i++) {
            int t  = tidx + i * 256;
            int kr = t >> 5;
            int n  = (t & 31) * 4;
            *reinterpret_cast<float4*>(&Bs[kr * 128 + n]) =
                *reinterpret_cast<const float4*>(Wout + (size_t)(kt * 16 + kr) * 128 + n);
        }
        __syncthreads();

        #pragma unroll
        for (int k = 0; k < 16; k++) {
            float a[8], bb[8];
            *reinterpret_cast<float4*>(&a[0]) =
                *reinterpret_cast<const float4*>(&As[k * 132 + ty * 8]);
            *reinterpret_cast<float4*>(&a[4]) =
                *reinterpret_cast<const float4*>(&As[k * 132 + ty * 8 + 4]);
            *reinterpret_cast<float4*>(&bb[0]) =
                *reinterpret_cast<const float4*>(&Bs[k * 128 + tx * 8]);
            *reinterpret_cast<float4*>(&bb[4]) =
                *reinterpret_cast<const float4*>(&Bs[k * 128 + tx * 8 + 4]);
            #pragma unroll
            for (int i = 0; i < 8; i++)
                #pragma unroll
                for (int j = 0; j < 8; j++)
                    acc[i][j] = fmaf(a[i], bb[j], acc[i][j]);
        }
        __syncthreads();
    }

    float bias[8];
    *reinterpret_cast<float4*>(&bias[0]) = *reinterpret_cast<const float4*>(&bout[tx * 8]);
    *reinterpret_cast<float4*>(&bias[4]) = *reinterpret_cast<const float4*>(&bout[tx * 8 + 4]);

    #pragma unroll
    for (int i = 0; i < 8; i++) {
        int row = r0 + ty * 8 + i;
        float4 o0, o1;
        o0.x = tanhf(acc[i][0] + bias[0]);
        o0.y = tanhf(acc[i][1] + bias[1]);
        o0.z = tanhf(acc[i][2] + bias[2]);
        o0.w = tanhf(acc[i][3] + bias[3]);
        o1.x = tanhf(acc[i][4] + bias[4]);
        o1.y = tanhf(acc[i][5] + bias[5]);
        o1.z = tanhf(acc[i][6] + bias[6]);
        o1.w = tanhf(acc[i][7] + bias[7]);
        *reinterpret_cast<float4*>(&out[(size_t)row * 128 + tx * 8])     = o0;
        *reinterpret_cast<float4*>(&out[(size_t)row * 128 + tx * 8 + 4]) = o1;
    }
}

// ============================================================
extern "C" void kernel_launch(void* const* d_in, const int* in_sizes, int n_in,
                              void* d_out, int out_size)
{
    const float* x    = (const float*)d_in[0];
    const float* Ws   = (const float*)d_in[2];
    const float* bs   = (const float*)d_in[3];
    const float* Wf   = (const float*)d_in[4];
    const float* bf   = (const float*)d_in[5];
    const float* Wout = (const float*)d_in[6];
    const float* bout = (const float*)d_in[7];
    float* out = (float*)d_out;

    k_transform<<<N_ / 64, 256>>>(x, Ws, bs, Wf, bf);
    k_knn<<<dim3(V_ / QW, B_), 512>>>();
    k_out<<<N_ / 128, 256>>>(x, Wout, bout, out);
}

// round 14
// speedup vs baseline: 4.8966x; 4.8966x over previous
#include <cuda_runtime.h>
#include <math.h>
#include <math_constants.h>

#define B_   32
#define V_   2048
#define K_   40
#define KP1  41
#define FIN  64
#define D_   4
#define P_   64
#define FILT 128
#define N_   (B_ * V_)
#define QW   8          // queries per block (512 thr, 16 warps, 2 warps/query)
#define FULL 0xffffffffu

// ---- scratch (static device arrays: no allocation allowed) ----
__device__ float g_coords[N_ * 4];                  // 1 MB
__device__ float g_feats[(size_t)N_ * FIN];         // 16 MB
__device__ float g_coll[(size_t)N_ * 2 * P_];       // 32 MB

// tiny no-op to shift ncu's -s 5 capture window onto a different kernel
__global__ void k_nop() {}

// ============================================================
// Kernel 1: coords = x@W_s + b_s ; feats = x@W_f + b_f
// ============================================================
__global__ void __launch_bounds__(256) k_transform(
    const float* __restrict__ x,
    const float* __restrict__ Ws, const float* __restrict__ bs,
    const float* __restrict__ Wf, const float* __restrict__ bf)
{
    __shared__ float xsT[64 * 65];
    __shared__ float wfs[64 * 64];
    __shared__ float wss[64 * 4];

    const int tid = threadIdx.x;
    const int r0 = blockIdx.x * 64;

    #pragma unroll
    for (int i = 0; i < 4; i++) {
        int f = tid + i * 256;
        reinterpret_cast<float4*>(wfs)[f] =
            reinterpret_cast<const float4*>(Wf)[f];
    }
    wss[tid] = Ws[tid];

    #pragma unroll
    for (int i = 0; i < 4; i++) {
        int f   = tid + i * 256;
        int row = f >> 4;
        int kq  = (f & 15) * 4;
        float4 v = *reinterpret_cast<const float4*>(
            x + (size_t)(r0 + row) * FIN + kq);
        xsT[(kq + 0) * 65 + row] = v.x;
        xsT[(kq + 1) * 65 + row] = v.y;
        xsT[(kq + 2) * 65 + row] = v.z;
        xsT[(kq + 3) * 65 + row] = v.w;
    }
    __syncthreads();

    const int tx = tid & 15, ty = tid >> 4;
    float acc[4][4];
    #pragma unroll
    for (int i = 0; i < 4; i++)
        #pragma unroll
        for (int j = 0; j < 4; j++) acc[i][j] = 0.f;

    #pragma unroll 16
    for (int k = 0; k < 64; k++) {
        float a0 = xsT[k * 65 + ty * 4 + 0];
        float a1 = xsT[k * 65 + ty * 4 + 1];
        float a2 = xsT[k * 65 + ty * 4 + 2];
        float a3 = xsT[k * 65 + ty * 4 + 3];
        float4 b = *reinterpret_cast<const float4*>(&wfs[k * 64 + tx * 4]);
        acc[0][0] = fmaf(a0, b.x, acc[0][0]); acc[0][1] = fmaf(a0, b.y, acc[0][1]);
        acc[0][2] = fmaf(a0, b.z, acc[0][2]); acc[0][3] = fmaf(a0, b.w, acc[0][3]);
        acc[1][0] = fmaf(a1, b.x, acc[1][0]); acc[1][1] = fmaf(a1, b.y, acc[1][1]);
        acc[1][2] = fmaf(a1, b.z, acc[1][2]); acc[1][3] = fmaf(a1, b.w, acc[1][3]);
        acc[2][0] = fmaf(a2, b.x, acc[2][0]); acc[2][1] = fmaf(a2, b.y, acc[2][1]);
        acc[2][2] = fmaf(a2, b.z, acc[2][2]); acc[2][3] = fmaf(a2, b.w, acc[2][3]);
        acc[3][0] = fmaf(a3, b.x, acc[3][0]); acc[3][1] = fmaf(a3, b.y, acc[3][1]);
        acc[3][2] = fmaf(a3, b.z, acc[3][2]); acc[3][3] = fmaf(a3, b.w, acc[3][3]);
    }

    float4 bfv = *reinterpret_cast<const float4*>(bf + tx * 4);
    #pragma unroll
    for (int i = 0; i < 4; i++) {
        int row = r0 + ty * 4 + i;
        float4 o;
        o.x = acc[i][0] + bfv.x; o.y = acc[i][1] + bfv.y;
        o.z = acc[i][2] + bfv.z; o.w = acc[i][3] + bfv.w;
        *reinterpret_cast<float4*>(g_feats + (size_t)row * FIN + tx * 4) = o;
    }

    {
        int crow = tid >> 2, cc = tid & 3;
        float a2 = 0.f;
        #pragma unroll 16
        for (int k = 0; k < 64; k++)
            a2 = fmaf(xsT[k * 65 + crow], wss[k * 4 + cc], a2);
        g_coords[(r0 + crow) * 4 + cc] = a2 + bs[cc];
    }
}

// ============================================================
// helpers
// ============================================================
__device__ __forceinline__ unsigned keyof(float d2) {
    unsigned u = __float_as_uint(d2);
    u ^= (u & 0x80000000u) ? 0xFFFFFFFFu : 0x80000000u;
    return u;
}
__device__ __forceinline__ unsigned long long ullmin_(unsigned long long a, unsigned long long b) {
    return a < b ? a : b;
}
__device__ __forceinline__ float sqnorm(float4 c) {
    float s = c.x * c.x;
    s = fmaf(c.y, c.y, s); s = fmaf(c.z, c.z, s); s = fmaf(c.w, c.w, s);
    return s;
}
__device__ __forceinline__ unsigned long long shfl_xor_u64(unsigned long long v, int st) {
    unsigned lo = (unsigned)(v & 0xffffffffull);
    unsigned hi = (unsigned)(v >> 32);
    lo = __shfl_xor_sync(FULL, lo, st);
    hi = __shfl_xor_sync(FULL, hi, st);
    return ((unsigned long long)hi << 32) | (unsigned long long)lo;
}
__device__ __forceinline__ void bstep_u32(unsigned &v, int ebase, int sz, int st, int lane) {
    unsigned o = __shfl_xor_sync(FULL, v, st);
    bool up    = ((ebase & sz) == 0);
    bool lower = ((lane & st) == 0);
    unsigned mn = min(v, o), mx = max(v, o);
    v = (lower == up) ? mn : mx;
}
__device__ __forceinline__ void bstep_u64(unsigned long long &v, int ebase, int sz, int st, int lane) {
    unsigned long long o = shfl_xor_u64(v, st);
    bool up    = ((ebase & sz) == 0);
    bool lower = ((lane & st) == 0);
    unsigned long long mn = v < o ? v : o;
    unsigned long long mx = v < o ? o : v;
    v = (lower == up) ? mn : mx;
}

// ascending sort of 128 u32 (4 regs/lane) — u32 copy of the R8-proven u64 net
__device__ __forceinline__ void sort128_u32(
    unsigned &c0, unsigned &c1, unsigned &c2, unsigned &c3, int lane)
{
    #pragma unroll
    for (int sz = 2; sz <= 32; sz <<= 1) {
        #pragma unroll
        for (int st = sz >> 1; st >= 1; st >>= 1) {
            bstep_u32(c0, lane,      sz, st, lane);
            bstep_u32(c1, 32 + lane, sz, st, lane);
            bstep_u32(c2, 64 + lane, sz, st, lane);
            bstep_u32(c3, 96 + lane, sz, st, lane);
        }
    }
    { unsigned mn = min(c0, c1), mx = max(c0, c1); c0 = mn; c1 = mx; }
    { unsigned mn = min(c2, c3), mx = max(c2, c3); c2 = mx; c3 = mn; }
    #pragma unroll
    for (int st = 16; st >= 1; st >>= 1) {
        bstep_u32(c0, lane,      64, st, lane);
        bstep_u32(c1, 32 + lane, 64, st, lane);
        bstep_u32(c2, 64 + lane, 64, st, lane);
        bstep_u32(c3, 96 + lane, 64, st, lane);
    }
    { unsigned mn = min(c0, c2), mx = max(c0, c2); c0 = mn; c2 = mx; }
    { unsigned mn = min(c1, c3), mx = max(c1, c3); c1 = mn; c3 = mx; }
    { unsigned mn = min(c0, c1), mx = max(c0, c1); c0 = mn; c1 = mx; }
    { unsigned mn = min(c2, c3), mx = max(c2, c3); c2 = mn; c3 = mx; }
    #pragma unroll
    for (int st = 16; st >= 1; st >>= 1) {
        bstep_u32(c0, lane,      128, st, lane);
        bstep_u32(c1, 32 + lane, 128, st, lane);
        bstep_u32(c2, 64 + lane, 128, st, lane);
        bstep_u32(c3, 96 + lane, 128, st, lane);
    }
}

// ascending sort of 64 u64 (2 regs/lane) — proven R8
__device__ __forceinline__ void sort64_u64(unsigned long long &c0, unsigned long long &c1, int lane) {
    #pragma unroll
    for (int sz = 2; sz <= 32; sz <<= 1) {
        #pragma unroll
        for (int st = sz >> 1; st >= 1; st >>= 1) {
            bstep_u64(c0, lane, sz, st, lane);
            bstep_u64(c1, 32 + lane, sz, st, lane);
        }
    }
    { unsigned long long mn = c0 < c1 ? c0 : c1, mx = c0 < c1 ? c1 : c0; c0 = mn; c1 = mx; }
    #pragma unroll
    for (int st = 16; st >= 1; st >>= 1) {
        bstep_u64(c0, lane, 64, st, lane);
        bstep_u64(c1, 32 + lane, 64, st, lane);
    }
}

// ascending sort of 128 u64 (4 regs/lane) — proven R8
__device__ __forceinline__ void sort128_u64(
    unsigned long long &c0, unsigned long long &c1,
    unsigned long long &c2, unsigned long long &c3, int lane)
{
    #pragma unroll
    for (int sz = 2; sz <= 32; sz <<= 1) {
        #pragma unroll
        for (int st = sz >> 1; st >= 1; st >>= 1) {
            bstep_u64(c0, lane,      sz, st, lane);
            bstep_u64(c1, 32 + lane, sz, st, lane);
            bstep_u64(c2, 64 + lane, sz, st, lane);
            bstep_u64(c3, 96 + lane, sz, st, lane);
        }
    }
    { unsigned long long mn = c0 < c1 ? c0 : c1, mx = c0 < c1 ? c1 : c0; c0 = mn; c1 = mx; }
    { unsigned long long mn = c2 < c3 ? c2 : c3, mx = c2 < c3 ? c3 : c2; c2 = mx; c3 = mn; }
    #pragma unroll
    for (int st = 16; st >= 1; st >>= 1) {
        bstep_u64(c0, lane,      64, st, lane);
        bstep_u64(c1, 32 + lane, 64, st, lane);
        bstep_u64(c2, 64 + lane, 64, st, lane);
        bstep_u64(c3, 96 + lane, 64, st, lane);
    }
    { unsigned long long mn = c0 < c2 ? c0 : c2, mx = c0 < c2 ? c2 : c0; c0 = mn; c2 = mx; }
    { unsigned long long mn = c1 < c3 ? c1 : c3, mx = c1 < c3 ? c3 : c1; c1 = mn; c3 = mx; }
    { unsigned long long mn = c0 < c1 ? c0 : c1, mx = c0 < c1 ? c1 : c0; c0 = mn; c1 = mx; }
    { unsigned long long mn = c2 < c3 ? c2 : c3, mx = c2 < c3 ? c3 : c2; c2 = mn; c3 = mx; }
    #pragma unroll
    for (int st = 16; st >= 1; st >>= 1) {
        bstep_u64(c0, lane,      128, st, lane);
        bstep_u64(c1, 32 + lane, 128, st, lane);
        bstep_u64(c2, 64 + lane, 128, st, lane);
        bstep_u64(c3, 96 + lane, 128, st, lane);
    }
}

// key of candidate idx = t*32+lane — identical fmaf chain everywhere
__device__ __forceinline__ unsigned keyat(const float4* sc, const float* ssq,
                                          float4 qc, float qsq, int t, int lane) {
    int idx = t * 32 + lane;
    float4 c = sc[idx];
    float dot = qc.x * c.x;
    dot = fmaf(qc.y, c.y, dot);
    dot = fmaf(qc.z, c.z, dot);
    dot = fmaf(qc.w, c.w, dot);
    float d2 = qsq + ssq[idx] - 2.f * dot;
    return keyof(d2);
}

// (weight, feature-base offset) for neighbor idx — reference weight form
__device__ __forceinline__ float2 wfor(const float4* sc, float4 qc, int idx) {
    float4 c = sc[idx];
    float dx = qc.x - c.x, dy = qc.y - c.y, dz = qc.z - c.z, dw = qc.w - c.w;
    float dist = dx * dx;
    dist = fmaf(dy, dy, dist);
    dist = fmaf(dz, dz, dist);
    dist = fmaf(dw, dw, dist);
    float2 r;
    r.x = expf(-fabsf(dist * 10.f));
    r.y = __int_as_float(idx << 6);
    return r;
}

// ---- ultra-rare exact fallback (nc > 128): one warp, keys from smem ----
__device__ __noinline__ void fb_exact(
    const float4* sc, const float* ssq, float2* cf,
    float4 qc, float qsq, unsigned gmin, unsigned Bq, int lane)
{
    const unsigned lanemask_lt = (1u << lane) - 1u;
    unsigned lo = gmin, hi = Bq;
    unsigned T = 0; int cT = 0; bool exact = false;
    while (lo < hi) {
        unsigned mid = lo + ((hi - lo) >> 1);
        int c = 0;
        for (int t = 0; t < 64; t++)
            c += (keyat(sc, ssq, qc, qsq, t, lane) <= mid) ? 1 : 0;
        c = __reduce_add_sync(FULL, c);
        if (c == KP1) {
            unsigned mx = 0;
            for (int t = 0; t < 64; t++) {
                unsigned u = keyat(sc, ssq, qc, qsq, t, lane);
                if (u <= mid) mx = max(mx, u);
            }
            T = __reduce_max_sync(FULL, mx);
            cT = KP1; exact = true; break;
        }
        if (c > KP1) hi = mid; else lo = mid + 1;
    }
    if (!exact) {
        T = lo;
        int c = 0;
        for (int t = 0; t < 64; t++)
            c += (keyat(sc, ssq, qc, qsq, t, lane) <= T) ? 1 : 0;
        cT = __reduce_add_sync(FULL, c);
    }
    unsigned long long selmask = 0ull;
    if (cT == KP1) {
        for (int t = 0; t < 64; t++)
            if (keyat(sc, ssq, qc, qsq, t, lane) <= T) selmask |= (1ull << t);
    } else {
        int c_less = 0;
        for (int t = 0; t < 64; t++)
            c_less += (keyat(sc, ssq, qc, qsq, t, lane) < T) ? 1 : 0;
        c_less = __reduce_add_sync(FULL, c_less);
        const int take_eq = KP1 - c_less;
        int running = 0;
        for (int t = 0; t < 64; t++) {
            unsigned u = keyat(sc, ssq, qc, qsq, t, lane);
            bool eq = (u == T);
            unsigned bal = __ballot_sync(FULL, eq);
            bool sel = (u < T);
            if (eq) {
                int rank = running + __popc(bal & lanemask_lt);
                sel = sel || (rank < take_eq);
            }
            running += __popc(bal);
            if (sel) selmask |= (1ull << t);
        }
    }
    unsigned long long mymin = 0xFFFFFFFFFFFFFFFFull;
    {
        unsigned long long m = selmask;
        while (m) {
            int t = __ffsll((long long)m) - 1;
            m &= m - 1;
            unsigned u = keyat(sc, ssq, qc, qsq, t, lane);
            mymin = ullmin_(mymin, ((unsigned long long)u << 32) | (unsigned)(t * 32 + lane));
        }
    }
    #pragma unroll
    for (int o = 16; o; o >>= 1)
        mymin = ullmin_(mymin, shfl_xor_u64(mymin, o));
    const int dropidx = (int)(unsigned)(mymin & 0xffffffffull);
    if ((dropidx & 31) == lane)
        selmask &= ~(1ull << (dropidx >> 5));
    int cnt = __popcll(selmask);
    int sc2 = cnt;
    #pragma unroll
    for (int o = 1; o < 32; o <<= 1) {
        int v = __shfl_up_sync(FULL, sc2, o);
        if (lane >= o) sc2 += v;
    }
    int p = sc2 - cnt;
    unsigned long long m = selmask;
    while (m) {
        int t = __ffsll((long long)m) - 1;
        m &= m - 1;
        if (p < K_) cf[p] = wfor(sc, qc, t * 32 + lane);
        p++;
    }
}

// ============================================================
// Kernel 2: exact KNN + pooling. 2 warps/query, merged tight bound,
// capacity-128 candidate sort (sort64/sort128 u64), feature-split pooling.
// ============================================================
__global__ void __launch_bounds__(512, 2) k_knn()
{
    __shared__ float4 sc[V_];                        // 32 KB
    __shared__ float  ssq[V_];                       // 8 KB
    __shared__ unsigned mins[QW][128];               // 4 KB (min2 values both halves)
    __shared__ unsigned long long cand[QW][128];     // 8 KB
    __shared__ unsigned sB[QW], sG[QW];
    __shared__ int s_cnt[QW];

    const int b   = blockIdx.y;
    const int tid = threadIdx.x;
    const float4* cg = reinterpret_cast<const float4*>(g_coords) + (size_t)b * V_;
    for (int t = tid; t < V_; t += 512) {
        float4 c = cg[t];
        sc[t]  = c;
        ssq[t] = sqnorm(c);
    }
    if (tid < QW) s_cnt[tid] = 0;
    __syncthreads();

    const int wid  = tid >> 5;
    const int lane = tid & 31;
    const int qq   = wid >> 1;          // query slot 0..7
    const int h    = wid & 1;           // half 0/1
    const int q    = blockIdx.x * QW + qq;

    const float4 qc  = sc[q];
    const float  qsq = ssq[q];
    const int base_idx = h * 1024;

    // ---- distance keys for own half + per-lane min2 ----
    unsigned key[32];
    unsigned m1 = 0xFFFFFFFFu, m2 = 0xFFFFFFFFu;
    #pragma unroll
    for (int j = 0; j < 32; j++) {
        int idx = base_idx + j * 32 + lane;
        float4 c = sc[idx];
        float dot = qc.x * c.x;
        dot = fmaf(qc.y, c.y, dot);
        dot = fmaf(qc.z, c.z, dot);
        dot = fmaf(qc.w, c.w, dot);
        float d2 = qsq + ssq[idx] - 2.f * dot;
        unsigned u = keyof(d2);
        key[j] = u;
        unsigned nm1 = min(m1, u);
        unsigned nm2 = min(m2, max(m1, u));
        m1 = nm1; m2 = nm2;
    }
    mins[qq][h * 64 + lane]      = m1;
    mins[qq][h * 64 + 32 + lane] = m2;
    __syncthreads();

    // ---- merged tight bound: 41st smallest of the 128 min2 values ----
    if (h == 0) {
        unsigned c0 = mins[qq][lane];
        unsigned c1 = mins[qq][32 + lane];
        unsigned c2 = mins[qq][64 + lane];
        unsigned c3 = mins[qq][96 + lane];
        sort128_u32(c0, c1, c2, c3, lane);
        if (lane == 8) sB[qq] = c1;   // element 40
        if (lane == 0) sG[qq] = c0;   // element 0 (global min key)
    }
    __syncthreads();
    const unsigned Bq   = sB[qq];     // count(keys <= Bq) >= 41 guaranteed
    const unsigned gmin = sG[qq];

    // ---- compact own half (key <= Bq) into shared candidate list ----
    {
        unsigned cm = 0;
        #pragma unroll
        for (int j = 0; j < 32; j++)
            if (key[j] <= Bq) cm |= (1u << j);
        int myc  = __popc(cm);
        int wtot = __reduce_add_sync(FULL, myc);
        int base = 0;
        if (lane == 0) base = atomicAdd(&s_cnt[qq], wtot);
        base = __shfl_sync(FULL, base, 0);
        int sc2 = myc;
        #pragma unroll
        for (int o = 1; o < 32; o <<= 1) {
            int v = __shfl_up_sync(FULL, sc2, o);
            if (lane >= o) sc2 += v;
        }
        int p = base + sc2 - myc;
        unsigned m = cm;
        while (m) {
            int j = __ffs(m) - 1;
            m &= m - 1;
            if (p < 128)
                cand[qq][p] = ((unsigned long long)key[j] << 32)
                            | (unsigned)(base_idx + j * 32 + lane);
            p++;
        }
    }
    __syncthreads();

    const int nc = s_cnt[qq];
    float2* cf = reinterpret_cast<float2*>(cand[qq]);

    // ---- composite sort; elements 1..40 = exact neighbor set ----
    if (h == 0 && nc <= 128) {
        const unsigned long long PADV = 0xFFFFFFFFFFFFFFFFull;
        unsigned long long c0 = (lane      < nc) ? cand[qq][lane]      : PADV;
        unsigned long long c1 = (32 + lane < nc) ? cand[qq][32 + lane] : PADV;
        if (nc <= 64) {
            sort64_u64(c0, c1, lane);
        } else {
            unsigned long long c2 = (64 + lane < nc) ? cand[qq][64 + lane] : PADV;
            unsigned long long c3 = (96 + lane < nc) ? cand[qq][96 + lane] : PADV;
            sort128_u64(c0, c1, c2, c3, lane);
        }
        int idx0 = (int)(unsigned)(c0 & 0xffffffffull);
        int idx1 = (int)(unsigned)(c1 & 0xffffffffull);
        __syncwarp();
        if (lane >= 1) cf[lane - 1]  = wfor(sc, qc, idx0);   // elems 1..31
        if (lane < 9)  cf[31 + lane] = wfor(sc, qc, idx1);   // elems 32..40
    }
    __syncthreads();

    if (nc > 128 && h == 0)
        fb_exact(sc, ssq, cf, qc, qsq, gmin, Bq, lane);
    __syncthreads();

    // ---- pooling: warp pair splits features; lane owns feature f ----
    const float* fb = g_feats + (size_t)b * V_ * FIN;
    const int f = h * 32 + lane;
    float mx = -CUDART_INF_F, sm = 0.f;
    #pragma unroll 8
    for (int n = 0; n < K_; n++) {
        float2 iw = cf[n];
        int off = __float_as_int(iw.y);      // idx*64
        float v = fb[off + f] * iw.x;
        mx = fmaxf(mx, v);
        sm += v;
    }
    float* o = g_coll + (size_t)(b * V_ + q) * (2 * P_);
    o[f]      = mx;
    o[64 + f] = sm * (1.f / (float)K_);
}

// ============================================================
// Kernel 3: out = tanh([x | collected] @ W_out + b_out)
// (R9 known-good single-buffered version)
// ============================================================
__global__ void __launch_bounds__(256) k_out(
    const float* __restrict__ x,
    const float* __restrict__ Wout, const float* __restrict__ bout,
    float* __restrict__ out)
{
    __shared__ float As[16 * 132];
    __shared__ float Bs[16 * 128];

    const int tidx = threadIdx.x;
    const int tx = tidx & 15, ty = tidx >> 4;
    const int r0 = blockIdx.x * 128;

    float acc[8][8];
    #pragma unroll
    for (int i = 0; i < 8; i++)
        #pragma unroll
        for (int j = 0; j < 8; j++) acc[i][j] = 0.f;

    for (int kt = 0; kt < 12; kt++) {
        #pragma unroll
        for (int i = 0; i < 2; i++) {
            int t   = tidx + i * 256;
            int row = t >> 2;
            int kq  = (t & 3) * 4;
            int gk  = kt * 16 + kq;
            const float* src = (gk < FIN)
                ? (x      + (size_t)(r0 + row) * FIN  + gk)
                : (g_coll + (size_t)(r0 + row) * 128 + (gk - FIN));
            float4 v = *reinterpret_cast<const float4*>(src);
            As[(kq + 0) * 132 + row] = v.x;
            As[(kq + 1) * 132 + row] = v.y;
            As[(kq + 2) * 132 + row] = v.z;
            As[(kq + 3) * 132 + row] = v.w;
        }
        #pragma unroll
        for (int i = 0; i < 2; i++) {
            int t  = tidx + i * 256;
            int kr = t >> 5;
            int n  = (t & 31) * 4;
            *reinterpret_cast<float4*>(&Bs[kr * 128 + n]) =
                *reinterpret_cast<const float4*>(Wout + (size_t)(kt * 16 + kr) * 128 + n);
        }
        __syncthreads();

        #pragma unroll
        for (int k = 0; k < 16; k++) {
            float a[8], bb[8];
            *reinterpret_cast<float4*>(&a[0]) =
                *reinterpret_cast<const float4*>(&As[k * 132 + ty * 8]);
            *reinterpret_cast<float4*>(&a[4]) =
                *reinterpret_cast<const float4*>(&As[k * 132 + ty * 8 + 4]);
            *reinterpret_cast<float4*>(&bb[0]) =
                *reinterpret_cast<const float4*>(&Bs[k * 128 + tx * 8]);
            *reinterpret_cast<float4*>(&bb[4]) =
                *reinterpret_cast<const float4*>(&Bs[k * 128 + tx * 8 + 4]);
            #pragma unroll
            for (int i = 0; i < 8; i++)
                #pragma unroll
                for (int j = 0; j < 8; j++)
                    acc[i][j] = fmaf(a[i], bb[j], acc[i][j]);
        }
        __syncthreads();
    }

    float bias[8];
    *reinterpret_cast<float4*>(&bias[0]) = *reinterpret_cast<const float4*>(&bout[tx * 8]);
    *reinterpret_cast<float4*>(&bias[4]) = *reinterpret_cast<const float4*>(&bout[tx * 8 + 4]);

    #pragma unroll
    for (int i = 0; i < 8; i++) {
        int row = r0 + ty * 8 + i;
        float4 o0, o1;
        o0.x = tanhf(acc[i][0] + bias[0]);
        o0.y = tanhf(acc[i][1] + bias[1]);
        o0.z = tanhf(acc[i][2] + bias[2]);
        o0.w = tanhf(acc[i][3] + bias[3]);
        o1.x = tanhf(acc[i][4] + bias[4]);
        o1.y = tanhf(acc[i][5] + bias[5]);
        o1.z = tanhf(acc[i][6] + bias[6]);
        o1.w = tanhf(acc[i][7] + bias[7]);
        *reinterpret_cast<float4*>(&out[(size_t)row * 128 + tx * 8])     = o0;
        *reinterpret_cast<float4*>(&out[(size_t)row * 128 + tx * 8 + 4]) = o1;
    }
}

// ============================================================
extern "C" void kernel_launch(void* const* d_in, const int* in_sizes, int n_in,
                              void* d_out, int out_size)
{
    const float* x    = (const float*)d_in[0];
    const float* Ws   = (const float*)d_in[2];
    const float* bs   = (const float*)d_in[3];
    const float* Wf   = (const float*)d_in[4];
    const float* bf   = (const float*)d_in[5];
    const float* Wout = (const float*)d_in[6];
    const float* bout = (const float*)d_in[7];
    float* out = (float*)d_out;

    k_nop<<<1, 32>>>();   // shifts ncu -s 5 capture window
    k_transform<<<N_ / 64, 256>>>(x, Ws, bs, Wf, bf);
    k_knn<<<dim3(V_ / QW, B_), 512>>>();
    k_out<<<N_ / 128, 256>>>(x, Wout, bout, out);
}

// round 15
// speedup vs baseline: 4.9233x; 1.0054x over previous
#include <cuda_runtime.h>
#include <math.h>
#include <math_constants.h>

#define B_   32
#define V_   2048
#define K_   40
#define KP1  41
#define FIN  64
#define D_   4
#define P_   64
#define FILT 128
#define N_   (B_ * V_)
#define QPB  8
#define FULL 0xffffffffu

// ---- scratch (static device arrays: no allocation allowed) ----
__device__ float g_coords[N_ * 4];                  // 1 MB
__device__ float g_feats[(size_t)N_ * FIN];         // 16 MB
__device__ float g_coll[(size_t)N_ * 2 * P_];       // 32 MB

// no-ops to place k_knn at launch #4 (ncu capture window)
__global__ void k_nop() {}

// ============================================================
// Kernel 1: coords = x@W_s + b_s ; feats = x@W_f + b_f
// ============================================================
__global__ void __launch_bounds__(256) k_transform(
    const float* __restrict__ x,
    const float* __restrict__ Ws, const float* __restrict__ bs,
    const float* __restrict__ Wf, const float* __restrict__ bf)
{
    __shared__ float xsT[64 * 65];
    __shared__ float wfs[64 * 64];
    __shared__ float wss[64 * 4];

    const int tid = threadIdx.x;
    const int r0 = blockIdx.x * 64;

    #pragma unroll
    for (int i = 0; i < 4; i++) {
        int f = tid + i * 256;
        reinterpret_cast<float4*>(wfs)[f] =
            reinterpret_cast<const float4*>(Wf)[f];
    }
    wss[tid] = Ws[tid];

    #pragma unroll
    for (int i = 0; i < 4; i++) {
        int f   = tid + i * 256;
        int row = f >> 4;
        int kq  = (f & 15) * 4;
        float4 v = *reinterpret_cast<const float4*>(
            x + (size_t)(r0 + row) * FIN + kq);
        xsT[(kq + 0) * 65 + row] = v.x;
        xsT[(kq + 1) * 65 + row] = v.y;
        xsT[(kq + 2) * 65 + row] = v.z;
        xsT[(kq + 3) * 65 + row] = v.w;
    }
    __syncthreads();

    const int tx = tid & 15, ty = tid >> 4;
    float acc[4][4];
    #pragma unroll
    for (int i = 0; i < 4; i++)
        #pragma unroll
        for (int j = 0; j < 4; j++) acc[i][j] = 0.f;

    #pragma unroll 16
    for (int k = 0; k < 64; k++) {
        float a0 = xsT[k * 65 + ty * 4 + 0];
        float a1 = xsT[k * 65 + ty * 4 + 1];
        float a2 = xsT[k * 65 + ty * 4 + 2];
        float a3 = xsT[k * 65 + ty * 4 + 3];
        float4 b = *reinterpret_cast<const float4*>(&wfs[k * 64 + tx * 4]);
        acc[0][0] = fmaf(a0, b.x, acc[0][0]); acc[0][1] = fmaf(a0, b.y, acc[0][1]);
        acc[0][2] = fmaf(a0, b.z, acc[0][2]); acc[0][3] = fmaf(a0, b.w, acc[0][3]);
        acc[1][0] = fmaf(a1, b.x, acc[1][0]); acc[1][1] = fmaf(a1, b.y, acc[1][1]);
        acc[1][2] = fmaf(a1, b.z, acc[1][2]); acc[1][3] = fmaf(a1, b.w, acc[1][3]);
        acc[2][0] = fmaf(a2, b.x, acc[2][0]); acc[2][1] = fmaf(a2, b.y, acc[2][1]);
        acc[2][2] = fmaf(a2, b.z, acc[2][2]); acc[2][3] = fmaf(a2, b.w, acc[2][3]);
        acc[3][0] = fmaf(a3, b.x, acc[3][0]); acc[3][1] = fmaf(a3, b.y, acc[3][1]);
        acc[3][2] = fmaf(a3, b.z, acc[3][2]); acc[3][3] = fmaf(a3, b.w, acc[3][3]);
    }

    float4 bfv = *reinterpret_cast<const float4*>(bf + tx * 4);
    #pragma unroll
    for (int i = 0; i < 4; i++) {
        int row = r0 + ty * 4 + i;
        float4 o;
        o.x = acc[i][0] + bfv.x; o.y = acc[i][1] + bfv.y;
        o.z = acc[i][2] + bfv.z; o.w = acc[i][3] + bfv.w;
        *reinterpret_cast<float4*>(g_feats + (size_t)row * FIN + tx * 4) = o;
    }

    {
        int crow = tid >> 2, cc = tid & 3;
        float a2 = 0.f;
        #pragma unroll 16
        for (int k = 0; k < 64; k++)
            a2 = fmaf(xsT[k * 65 + crow], wss[k * 4 + cc], a2);
        g_coords[(r0 + crow) * 4 + cc] = a2 + bs[cc];
    }
}

// ============================================================
// warp bitonic sort of 64 u32 (2 regs/lane, element e = r*32+lane)
// ============================================================
__device__ __forceinline__ void bstep_u32(unsigned &v, int ebase, int sz, int st, int lane) {
    unsigned o = __shfl_xor_sync(FULL, v, st);
    bool up    = ((ebase & sz) == 0);
    bool lower = ((lane & st) == 0);
    unsigned mn = min(v, o), mx = max(v, o);
    v = (lower == up) ? mn : mx;
}

__device__ __forceinline__ void sort64_u32(unsigned &s0, unsigned &s1, int lane) {
    #pragma unroll
    for (int sz = 2; sz <= 32; sz <<= 1) {
        #pragma unroll
        for (int st = sz >> 1; st >= 1; st >>= 1) {
            bstep_u32(s0, lane, sz, st, lane);
            bstep_u32(s1, 32 + lane, sz, st, lane);
        }
    }
    { unsigned mn = min(s0, s1), mx = max(s0, s1); s0 = mn; s1 = mx; }
    #pragma unroll
    for (int st = 16; st >= 1; st >>= 1) {
        bstep_u32(s0, lane, 64, st, lane);
        bstep_u32(s1, 32 + lane, 64, st, lane);
    }
}

// ============================================================
// Kernel 2: exact KNN + Gaussian-weighted max/mean pooling.
// (R9 configuration — best measured)
// ============================================================
__device__ __forceinline__ unsigned keyof(float d2) {
    unsigned u = __float_as_uint(d2);
    u ^= (u & 0x80000000u) ? 0xFFFFFFFFu : 0x80000000u;
    return u;
}
__device__ __forceinline__ unsigned long long ullmin_(unsigned long long a, unsigned long long b) {
    return a < b ? a : b;
}

__global__ void __launch_bounds__(256, 2) k_knn()
{
    __shared__ float4 sc[V_];                      // 32 KB
    __shared__ float  ssq[V_];                     // 8 KB
    __shared__ unsigned candk[QPB][64];            // 2 KB (candidate keys)
    __shared__ float2 s_iw[QPB][K_];               // 2.5 KB (weight, idx)

    const int b   = blockIdx.y;
    const int tid = threadIdx.x;
    const float4* cg = reinterpret_cast<const float4*>(g_coords) + (size_t)b * V_;
    for (int t = tid; t < V_; t += 256) {
        float4 c = cg[t];
        sc[t]  = c;
        float s = c.x * c.x;
        s = fmaf(c.y, c.y, s); s = fmaf(c.z, c.z, s); s = fmaf(c.w, c.w, s);
        ssq[t] = s;
    }
    __syncthreads();

    const int w    = tid >> 5;
    const int lane = tid & 31;
    const int q    = blockIdx.x * QPB + w;
    const unsigned lanemask_lt = (1u << lane) - 1u;

    const float4 qc  = sc[q];
    const float  qsq = ssq[q];

    // ---- distance keys + fused per-lane two smallest ----
    unsigned key[64];
    unsigned m1 = 0xFFFFFFFFu, m2 = 0xFFFFFFFFu;
    #pragma unroll
    for (int j = 0; j < 64; j++) {
        int idx = j * 32 + lane;
        float4 c = sc[idx];
        float dot = qc.x * c.x;
        dot = fmaf(qc.y, c.y, dot);
        dot = fmaf(qc.z, c.z, dot);
        dot = fmaf(qc.w, c.w, dot);
        float d2 = qsq + ssq[idx] - 2.f * dot;
        unsigned u = keyof(d2);
        key[j] = u;
        unsigned nm1 = min(m1, u);
        unsigned nm2 = min(m2, max(m1, u));
        m1 = nm1; m2 = nm2;
    }

    // ---- B = 41st smallest of min2 union (upper bound on threshold) ----
    unsigned s0 = m1, s1 = m2;
    sort64_u32(s0, s1, lane);
    const unsigned B    = __shfl_sync(FULL, s1, 8);   // element 40
    const unsigned gmin = __shfl_sync(FULL, s0, 0);   // element 0

    // ---- candidate membership mask (key <= B), prefix-scan compaction ----
    unsigned long long candmask = 0ull;
    #pragma unroll
    for (int j = 0; j < 64; j++)
        if (key[j] <= B) candmask |= (1ull << j);

    int myCnt = __popcll(candmask);
    int scan = myCnt;
    #pragma unroll
    for (int o = 1; o < 32; o <<= 1) {
        int v = __shfl_up_sync(FULL, scan, o);
        if (lane >= o) scan += v;
    }
    const int nc   = __shfl_sync(FULL, scan, 31);
    int pos = scan - myCnt;

    unsigned long long selmask = 0ull;   // final selected set (41 incl drop)

    if (nc <= 64) {
        // ======== FAST PATH ========
        {
            unsigned long long m = candmask;
            while (m) {
                int j = __ffsll((long long)m) - 1;
                m &= m - 1;
                candk[w][pos++] = key[j];
            }
        }
        __syncwarp();
        unsigned c0 = (lane      < nc) ? candk[w][lane]      : 0xFFFFFFFFu;
        unsigned c1 = (32 + lane < nc) ? candk[w][32 + lane] : 0xFFFFFFFFu;
        sort64_u32(c0, c1, lane);
        const unsigned T  = __shfl_sync(FULL, c1, 8);    // element 40 = 41st key
        const unsigned T1 = __shfl_sync(FULL, c1, 9);    // element 41
        const bool tie = (nc >= 42) && (T1 == T);

        if (!tie) {
            #pragma unroll
            for (int j = 0; j < 64; j++)
                if (key[j] <= T) selmask |= (1ull << j);
        } else {
            int c_less = 0;
            #pragma unroll
            for (int j = 0; j < 64; j++) c_less += (key[j] < T) ? 1 : 0;
            c_less = __reduce_add_sync(FULL, c_less);
            const int take_eq = KP1 - c_less;
            int running = 0;
            #pragma unroll
            for (int j = 0; j < 64; j++) {
                bool eq = (key[j] == T);
                unsigned bal = __ballot_sync(FULL, eq);
                bool sel = (key[j] < T);
                if (eq) {
                    int rank = running + __popc(bal & lanemask_lt);
                    sel = sel || (rank < take_eq);
                }
                running += __popc(bal);
                if (sel) selmask |= (1ull << j);
            }
        }
    } else {
        // ======== FALLBACK (degenerate): exact binary search ========
        unsigned lo = gmin, hi = B;
        unsigned T = 0;
        int cT = 0;
        bool exact = false;
        while (lo < hi) {
            unsigned mid = lo + ((hi - lo) >> 1);
            int c = 0;
            #pragma unroll
            for (int j = 0; j < 64; j++) c += (key[j] <= mid) ? 1 : 0;
            c = __reduce_add_sync(FULL, c);
            if (c == KP1) {
                unsigned mx = 0;
                #pragma unroll
                for (int j = 0; j < 64; j++) if (key[j] <= mid) mx = max(mx, key[j]);
                T = __reduce_max_sync(FULL, mx);
                cT = KP1; exact = true; break;
            }
            if (c > KP1) hi = mid; else lo = mid + 1;
        }
        if (!exact) {
            T = lo;
            int c = 0;
            #pragma unroll
            for (int j = 0; j < 64; j++) c += (key[j] <= T) ? 1 : 0;
            cT = __reduce_add_sync(FULL, c);
        }
        if (cT == KP1) {
            #pragma unroll
            for (int j = 0; j < 64; j++)
                if (key[j] <= T) selmask |= (1ull << j);
        } else {
            int c_less = 0;
            #pragma unroll
            for (int j = 0; j < 64; j++) c_less += (key[j] < T) ? 1 : 0;
            c_less = __reduce_add_sync(FULL, c_less);
            const int take_eq = KP1 - c_less;
            int running = 0;
            #pragma unroll
            for (int j = 0; j < 64; j++) {
                bool eq = (key[j] == T);
                unsigned bal = __ballot_sync(FULL, eq);
                bool sel = (key[j] < T);
                if (eq) {
                    int rank = running + __popc(bal & lanemask_lt);
                    sel = sel || (rank < take_eq);
                }
                running += __popc(bal);
                if (sel) selmask |= (1ull << j);
            }
        }
    }

    // ---- common epilogue: drop = min composite; write (weight, idx) ----
    unsigned long long mymin = 0xFFFFFFFFFFFFFFFFull;
    {
        unsigned long long m = selmask;
        while (m) {
            int j = __ffsll((long long)m) - 1;
            m &= m - 1;
            unsigned long long ck =
                ((unsigned long long)key[j] << 32) | (unsigned)(j * 32 + lane);
            mymin = ullmin_(mymin, ck);
        }
    }
    #pragma unroll
    for (int o = 16; o; o >>= 1)
        mymin = ullmin_(mymin, __shfl_xor_sync(FULL, mymin, o));
    const int dropidx = (int)(unsigned)(mymin & 0xffffffffull);
    if ((dropidx & 31) == lane)
        selmask &= ~(1ull << (dropidx >> 5));

    {
        int cnt = __popcll(selmask);
        int sc2 = cnt;
        #pragma unroll
        for (int o = 1; o < 32; o <<= 1) {
            int v = __shfl_up_sync(FULL, sc2, o);
            if (lane >= o) sc2 += v;
        }
        int p = sc2 - cnt;
        unsigned long long m = selmask;
        while (m) {
            int j = __ffsll((long long)m) - 1;
            m &= m - 1;
            int idx = j * 32 + lane;
            float4 c = sc[idx];
            float dx = qc.x - c.x, dy = qc.y - c.y, dz = qc.z - c.z, dw = qc.w - c.w;
            float dist = dx * dx;
            dist = fmaf(dy, dy, dist);
            dist = fmaf(dz, dz, dist);
            dist = fmaf(dw, dw, dist);
            float2 iw;
            iw.x = expf(-fabsf(dist * 10.f));
            iw.y = __int_as_float(idx);
            if (p < K_) s_iw[w][p] = iw;
            p++;
        }
    }
    __syncwarp();

    // ---- weighted max / mean pooling over the 40 neighbors ----
    const float* fb = g_feats + (size_t)b * V_ * FIN;
    float mx0 = -CUDART_INF_F, mx1 = -CUDART_INF_F, sm0 = 0.f, sm1 = 0.f;
    #pragma unroll 8
    for (int n = 0; n < K_; n++) {
        float2 iw = s_iw[w][n];
        int   idx = __float_as_int(iw.y);
        float wt  = iw.x;
        float f0 = fb[(size_t)idx * FIN + lane];
        float f1 = fb[(size_t)idx * FIN + 32 + lane];
        float v0 = f0 * wt, v1 = f1 * wt;
        mx0 = fmaxf(mx0, v0); mx1 = fmaxf(mx1, v1);
        sm0 += v0;            sm1 += v1;
    }
    const int grow = b * V_ + q;
    float* o = g_coll + (size_t)grow * (2 * P_);
    o[lane]       = mx0;
    o[32 + lane]  = mx1;
    o[64 + lane]  = sm0 * (1.f / (float)K_);
    o[96 + lane]  = sm1 * (1.f / (float)K_);
}

// ============================================================
// Kernel 3: out = tanh([x | collected] @ W_out + b_out)
// (single-buffered; measured at ~93% of FFMA roofline)
// ============================================================
__global__ void __launch_bounds__(256) k_out(
    const float* __restrict__ x,
    const float* __restrict__ Wout, const float* __restrict__ bout,
    float* __restrict__ out)
{
    __shared__ float As[16 * 132];
    __shared__ float Bs[16 * 128];

    const int tidx = threadIdx.x;
    const int tx = tidx & 15, ty = tidx >> 4;
    const int r0 = blockIdx.x * 128;

    float acc[8][8];
    #pragma unroll
    for (int i = 0; i < 8; i++)
        #pragma unroll
        for (int j = 0; j < 8; j++) acc[i][j] = 0.f;

    for (int kt = 0; kt < 12; kt++) {
        #pragma unroll
        for (int i = 0; i < 2; i++) {
            int t   = tidx + i * 256;
            int row = t >> 2;
            int kq  = (t & 3) * 4;
            int gk  = kt * 16 + kq;
            const float* src = (gk < FIN)
                ? (x      + (size_t)(r0 + row) * FIN  + gk)
                : (g_coll + (size_t)(r0 + row) * 128 + (gk - FIN));
            float4 v = *reinterpret_cast<const float4*>(src);
            As[(kq + 0) * 132 + row] = v.x;
            As[(kq + 1) * 132 + row] = v.y;
            As[(kq + 2) * 132 + row] = v.z;
            As[(kq + 3) * 132 + row] = v.w;
        }
        #pragma unroll
        for (int i = 0; i < 2; i++) {
            int t  = tidx + i * 256;
            int kr = t >> 5;
            int n  = (t & 31) * 4;
            *reinterpret_cast<float4*>(&Bs[kr * 128 + n]) =
                *reinterpret_cast<const float4*>(Wout + (size_t)(kt * 16 + kr) * 128 + n);
        }
        __syncthreads();

        #pragma unroll
        for (int k = 0; k < 16; k++) {
            float a[8], bb[8];
            *reinterpret_cast<float4*>(&a[0]) =
                *reinterpret_cast<const float4*>(&As[k * 132 + ty * 8]);
            *reinterpret_cast<float4*>(&a[4]) =
                *reinterpret_cast<const float4*>(&As[k * 132 + ty * 8 + 4]);
            *reinterpret_cast<float4*>(&bb[0]) =
                *reinterpret_cast<const float4*>(&Bs[k * 128 + tx * 8]);
            *reinterpret_cast<float4*>(&bb[4]) =
                *reinterpret_cast<const float4*>(&Bs[k * 128 + tx * 8 + 4]);
            #pragma unroll
            for (int i = 0; i < 8; i++)
                #pragma unroll
                for (int j = 0; j < 8; j++)
                    acc[i][j] = fmaf(a[i], bb[j], acc[i][j]);
        }
        __syncthreads();
    }

    float bias[8];
    *reinterpret_cast<float4*>(&bias[0]) = *reinterpret_cast<const float4*>(&bout[tx * 8]);
    *reinterpret_cast<float4*>(&bias[4]) = *reinterpret_cast<const float4*>(&bout[tx * 8 + 4]);

    #pragma unroll
    for (int i = 0; i < 8; i++) {
        int row = r0 + ty * 8 + i;
        float4 o0, o1;
        o0.x = tanhf(acc[i][0] + bias[0]);
        o0.y = tanhf(acc[i][1] + bias[1]);
        o0.z = tanhf(acc[i][2] + bias[2]);
        o0.w = tanhf(acc[i][3] + bias[3]);
        o1.x = tanhf(acc[i][4] + bias[4]);
        o1.y = tanhf(acc[i][5] + bias[5]);
        o1.z = tanhf(acc[i][6] + bias[6]);
        o1.w = tanhf(acc[i][7] + bias[7]);
        *reinterpret_cast<float4*>(&out[(size_t)row * 128 + tx * 8])     = o0;
        *reinterpret_cast<float4*>(&out[(size_t)row * 128 + tx * 8 + 4]) = o1;
    }
}

// ============================================================
extern "C" void kernel_launch(void* const* d_in, const int* in_sizes, int n_in,
                              void* d_out, int out_size)
{
    const float* x    = (const float*)d_in[0];
    const float* Ws   = (const float*)d_in[2];
    const float* bs   = (const float*)d_in[3];
    const float* Wf   = (const float*)d_in[4];
    const float* bf   = (const float*)d_in[5];
    const float* Wout = (const float*)d_in[6];
    const float* bout = (const float*)d_in[7];
    float* out = (float*)d_out;

    // launch order places k_knn at launch #4 = ncu capture slot
    k_transform<<<N_ / 64, 256>>>(x, Ws, bs, Wf, bf);   // #1
    k_nop<<<1, 32>>>();                                  // #2
    k_nop<<<1, 32>>>();                                  // #3
    k_knn<<<dim3(V_ / QPB, B_), 256>>>();                // #4  <- profiled
    k_out<<<N_ / 128, 256>>>(x, Wout, bout, out);        // #5
}

// round 16
// speedup vs baseline: 5.8424x; 1.1867x over previous
#include <cuda_runtime.h>
#include <math.h>
#include <math_constants.h>

#define B_   32
#define V_   2048
#define K_   40
#define KP1  41
#define FIN  64
#define D_   4
#define P_   64
#define FILT 128
#define N_   (B_ * V_)
#define QPB  8
#define FULL 0xffffffffu

// ---- scratch (static device arrays: no allocation allowed) ----
__device__ float g_coords[N_ * 4];                  // 1 MB
__device__ float g_feats[(size_t)N_ * FIN];         // 16 MB
__device__ float g_coll[(size_t)N_ * 2 * P_];       // 32 MB

// no-ops to place k_knn at launch #4 (ncu capture window)
__global__ void k_nop() {}

// ============================================================
// Kernel 1: coords = x@W_s + b_s ; feats = x@W_f + b_f
// ============================================================
__global__ void __launch_bounds__(256) k_transform(
    const float* __restrict__ x,
    const float* __restrict__ Ws, const float* __restrict__ bs,
    const float* __restrict__ Wf, const float* __restrict__ bf)
{
    __shared__ float xsT[64 * 65];
    __shared__ float wfs[64 * 64];
    __shared__ float wss[64 * 4];

    const int tid = threadIdx.x;
    const int r0 = blockIdx.x * 64;

    #pragma unroll
    for (int i = 0; i < 4; i++) {
        int f = tid + i * 256;
        reinterpret_cast<float4*>(wfs)[f] =
            reinterpret_cast<const float4*>(Wf)[f];
    }
    wss[tid] = Ws[tid];

    #pragma unroll
    for (int i = 0; i < 4; i++) {
        int f   = tid + i * 256;
        int row = f >> 4;
        int kq  = (f & 15) * 4;
        float4 v = *reinterpret_cast<const float4*>(
            x + (size_t)(r0 + row) * FIN + kq);
        xsT[(kq + 0) * 65 + row] = v.x;
        xsT[(kq + 1) * 65 + row] = v.y;
        xsT[(kq + 2) * 65 + row] = v.z;
        xsT[(kq + 3) * 65 + row] = v.w;
    }
    __syncthreads();

    const int tx = tid & 15, ty = tid >> 4;
    float acc[4][4];
    #pragma unroll
    for (int i = 0; i < 4; i++)
        #pragma unroll
        for (int j = 0; j < 4; j++) acc[i][j] = 0.f;

    #pragma unroll 16
    for (int k = 0; k < 64; k++) {
        float a0 = xsT[k * 65 + ty * 4 + 0];
        float a1 = xsT[k * 65 + ty * 4 + 1];
        float a2 = xsT[k * 65 + ty * 4 + 2];
        float a3 = xsT[k * 65 + ty * 4 + 3];
        float4 b = *reinterpret_cast<const float4*>(&wfs[k * 64 + tx * 4]);
        acc[0][0] = fmaf(a0, b.x, acc[0][0]); acc[0][1] = fmaf(a0, b.y, acc[0][1]);
        acc[0][2] = fmaf(a0, b.z, acc[0][2]); acc[0][3] = fmaf(a0, b.w, acc[0][3]);
        acc[1][0] = fmaf(a1, b.x, acc[1][0]); acc[1][1] = fmaf(a1, b.y, acc[1][1]);
        acc[1][2] = fmaf(a1, b.z, acc[1][2]); acc[1][3] = fmaf(a1, b.w, acc[1][3]);
        acc[2][0] = fmaf(a2, b.x, acc[2][0]); acc[2][1] = fmaf(a2, b.y, acc[2][1]);
        acc[2][2] = fmaf(a2, b.z, acc[2][2]); acc[2][3] = fmaf(a2, b.w, acc[2][3]);
        acc[3][0] = fmaf(a3, b.x, acc[3][0]); acc[3][1] = fmaf(a3, b.y, acc[3][1]);
        acc[3][2] = fmaf(a3, b.z, acc[3][2]); acc[3][3] = fmaf(a3, b.w, acc[3][3]);
    }

    float4 bfv = *reinterpret_cast<const float4*>(bf + tx * 4);
    #pragma unroll
    for (int i = 0; i < 4; i++) {
        int row = r0 + ty * 4 + i;
        float4 o;
        o.x = acc[i][0] + bfv.x; o.y = acc[i][1] + bfv.y;
        o.z = acc[i][2] + bfv.z; o.w = acc[i][3] + bfv.w;
        *reinterpret_cast<float4*>(g_feats + (size_t)row * FIN + tx * 4) = o;
    }

    {
        int crow = tid >> 2, cc = tid & 3;
        float a2 = 0.f;
        #pragma unroll 16
        for (int k = 0; k < 64; k++)
            a2 = fmaf(xsT[k * 65 + crow], wss[k * 4 + cc], a2);
        g_coords[(r0 + crow) * 4 + cc] = a2 + bs[cc];
    }
}

// ============================================================
// helpers
// ============================================================
__device__ __forceinline__ unsigned keyof(float d2) {
    unsigned u = __float_as_uint(d2);
    u ^= (u & 0x80000000u) ? 0xFFFFFFFFu : 0x80000000u;
    return u;
}
__device__ __forceinline__ unsigned long long ullmin_(unsigned long long a, unsigned long long b) {
    return a < b ? a : b;
}
__device__ __forceinline__ unsigned long long shfl_xor_u64(unsigned long long v, int st) {
    unsigned lo = (unsigned)(v & 0xffffffffull);
    unsigned hi = (unsigned)(v >> 32);
    lo = __shfl_xor_sync(FULL, lo, st);
    hi = __shfl_xor_sync(FULL, hi, st);
    return ((unsigned long long)hi << 32) | (unsigned long long)lo;
}
__device__ __forceinline__ void bstep_u32(unsigned &v, int ebase, int sz, int st, int lane) {
    unsigned o = __shfl_xor_sync(FULL, v, st);
    bool up    = ((ebase & sz) == 0);
    bool lower = ((lane & st) == 0);
    unsigned mn = min(v, o), mx = max(v, o);
    v = (lower == up) ? mn : mx;
}
__device__ __forceinline__ void bstep_u64(unsigned long long &v, int ebase, int sz, int st, int lane) {
    unsigned long long o = shfl_xor_u64(v, st);
    bool up    = ((ebase & sz) == 0);
    bool lower = ((lane & st) == 0);
    unsigned long long mn = v < o ? v : o;
    unsigned long long mx = v < o ? o : v;
    v = (lower == up) ? mn : mx;
}
// ascending sort of 64 u32 (2 regs/lane, element e = r*32+lane)
__device__ __forceinline__ void sort64_u32(unsigned &s0, unsigned &s1, int lane) {
    #pragma unroll
    for (int sz = 2; sz <= 32; sz <<= 1) {
        #pragma unroll
        for (int st = sz >> 1; st >= 1; st >>= 1) {
            bstep_u32(s0, lane, sz, st, lane);
            bstep_u32(s1, 32 + lane, sz, st, lane);
        }
    }
    { unsigned mn = min(s0, s1), mx = max(s0, s1); s0 = mn; s1 = mx; }
    #pragma unroll
    for (int st = 16; st >= 1; st >>= 1) {
        bstep_u32(s0, lane, 64, st, lane);
        bstep_u32(s1, 32 + lane, 64, st, lane);
    }
}
// ascending sort of 64 u64 (2 regs/lane) — proven R8
__device__ __forceinline__ void sort64_u64(unsigned long long &c0, unsigned long long &c1, int lane) {
    #pragma unroll
    for (int sz = 2; sz <= 32; sz <<= 1) {
        #pragma unroll
        for (int st = sz >> 1; st >= 1; st >>= 1) {
            bstep_u64(c0, lane, sz, st, lane);
            bstep_u64(c1, 32 + lane, sz, st, lane);
        }
    }
    { unsigned long long mn = c0 < c1 ? c0 : c1, mx = c0 < c1 ? c1 : c0; c0 = mn; c1 = mx; }
    #pragma unroll
    for (int st = 16; st >= 1; st >>= 1) {
        bstep_u64(c0, lane, 64, st, lane);
        bstep_u64(c1, 32 + lane, 64, st, lane);
    }
}

// key of candidate idx = t*32+lane — identical fmaf chain everywhere
__device__ __forceinline__ unsigned keyat(const float4* sc, const float* ssq,
                                          float4 qc, float qsq, int t, int lane) {
    int idx = t * 32 + lane;
    float4 c = sc[idx];
    float dot = qc.x * c.x;
    dot = fmaf(qc.y, c.y, dot);
    dot = fmaf(qc.z, c.z, dot);
    dot = fmaf(qc.w, c.w, dot);
    float d2 = qsq + ssq[idx] - 2.f * dot;
    return keyof(d2);
}

// (weight, feature-base offset) for neighbor idx — reference weight form
__device__ __forceinline__ float2 wfor(const float4* sc, float4 qc, int idx) {
    float4 c = sc[idx];
    float dx = qc.x - c.x, dy = qc.y - c.y, dz = qc.z - c.z, dw = qc.w - c.w;
    float dist = dx * dx;
    dist = fmaf(dy, dy, dist);
    dist = fmaf(dz, dz, dist);
    dist = fmaf(dw, dw, dist);
    float2 r;
    r.x = expf(-fabsf(dist * 10.f));
    r.y = __int_as_float(idx << 6);   // element offset idx*FIN
    return r;
}

// ---- rare exact fallback (nc > 64): streaming keys from smem ----
__device__ __noinline__ void fb_exact(
    const float4* sc, const float* ssq, float2* cf,
    float4 qc, float qsq, unsigned gmin, unsigned Bq, int lane)
{
    const unsigned lanemask_lt = (1u << lane) - 1u;
    unsigned lo = gmin, hi = Bq;
    unsigned T = 0; int cT = 0; bool exact = false;
    while (lo < hi) {
        unsigned mid = lo + ((hi - lo) >> 1);
        int c = 0;
        for (int t = 0; t < 64; t++)
            c += (keyat(sc, ssq, qc, qsq, t, lane) <= mid) ? 1 : 0;
        c = __reduce_add_sync(FULL, c);
        if (c == KP1) {
            unsigned mx = 0;
            for (int t = 0; t < 64; t++) {
                unsigned u = keyat(sc, ssq, qc, qsq, t, lane);
                if (u <= mid) mx = max(mx, u);
            }
            T = __reduce_max_sync(FULL, mx);
            cT = KP1; exact = true; break;
        }
        if (c > KP1) hi = mid; else lo = mid + 1;
    }
    if (!exact) {
        T = lo;
        int c = 0;
        for (int t = 0; t < 64; t++)
            c += (keyat(sc, ssq, qc, qsq, t, lane) <= T) ? 1 : 0;
        cT = __reduce_add_sync(FULL, c);
    }
    unsigned long long selmask = 0ull;
    if (cT == KP1) {
        for (int t = 0; t < 64; t++)
            if (keyat(sc, ssq, qc, qsq, t, lane) <= T) selmask |= (1ull << t);
    } else {
        int c_less = 0;
        for (int t = 0; t < 64; t++)
            c_less += (keyat(sc, ssq, qc, qsq, t, lane) < T) ? 1 : 0;
        c_less = __reduce_add_sync(FULL, c_less);
        const int take_eq = KP1 - c_less;
        int running = 0;
        for (int t = 0; t < 64; t++) {
            unsigned u = keyat(sc, ssq, qc, qsq, t, lane);
            bool eq = (u == T);
            unsigned bal = __ballot_sync(FULL, eq);
            bool sel = (u < T);
            if (eq) {
                int rank = running + __popc(bal & lanemask_lt);
                sel = sel || (rank < take_eq);
            }
            running += __popc(bal);
            if (sel) selmask |= (1ull << t);
        }
    }
    unsigned long long mymin = 0xFFFFFFFFFFFFFFFFull;
    {
        unsigned long long m = selmask;
        while (m) {
            int t = __ffsll((long long)m) - 1;
            m &= m - 1;
            unsigned u = keyat(sc, ssq, qc, qsq, t, lane);
            mymin = ullmin_(mymin, ((unsigned long long)u << 32) | (unsigned)(t * 32 + lane));
        }
    }
    #pragma unroll
    for (int o = 16; o; o >>= 1)
        mymin = ullmin_(mymin, shfl_xor_u64(mymin, o));
    const int dropidx = (int)(unsigned)(mymin & 0xffffffffull);
    if ((dropidx & 31) == lane)
        selmask &= ~(1ull << (dropidx >> 5));
    int cnt = __popcll(selmask);
    int sc2 = cnt;
    #pragma unroll
    for (int o = 1; o < 32; o <<= 1) {
        int v = __shfl_up_sync(FULL, sc2, o);
        if (lane >= o) sc2 += v;
    }
    int p = sc2 - cnt;
    unsigned long long m = selmask;
    while (m) {
        int t = __ffsll((long long)m) - 1;
        m &= m - 1;
        if (p < K_) cf[p] = wfor(sc, qc, t * 32 + lane);
        p++;
    }
}

// ============================================================
// Kernel 2: exact KNN + pooling. TWO-PASS STREAMING:
// no key array in registers -> regs ~55 -> 32 warps/SM.
// Pass 1: min2 bound. Pass 2: recompute + compact composites.
// sort64_u64: elem 0 = drop, 1..40 = exact lax.top_k neighbor set.
// ============================================================
__global__ void __launch_bounds__(256, 4) k_knn()
{
    __shared__ float4 sc[V_];                        // 32 KB
    __shared__ float  ssq[V_];                       // 8 KB
    __shared__ unsigned long long cand[QPB][64];     // 4 KB

    const int b   = blockIdx.y;
    const int tid = threadIdx.x;
    const float4* cg = reinterpret_cast<const float4*>(g_coords) + (size_t)b * V_;
    for (int t = tid; t < V_; t += 256) {
        float4 c = cg[t];
        sc[t]  = c;
        float s = c.x * c.x;
        s = fmaf(c.y, c.y, s); s = fmaf(c.z, c.z, s); s = fmaf(c.w, c.w, s);
        ssq[t] = s;
    }
    __syncthreads();

    const int w    = tid >> 5;
    const int lane = tid & 31;
    const int q    = blockIdx.x * QPB + w;

    const float4 qc  = sc[q];
    const float  qsq = ssq[q];

    // ---- PASS 1: per-lane min2 via two interleaved chains ----
    unsigned m1a = 0xFFFFFFFFu, m2a = 0xFFFFFFFFu;
    unsigned m1b = 0xFFFFFFFFu, m2b = 0xFFFFFFFFu;
    #pragma unroll
    for (int j = 0; j < 64; j += 2) {
        unsigned u0 = keyat(sc, ssq, qc, qsq, j,     lane);
        unsigned u1 = keyat(sc, ssq, qc, qsq, j + 1, lane);
        unsigned ta = max(m1a, u0); m1a = min(m1a, u0); m2a = min(m2a, ta);
        unsigned tb = max(m1b, u1); m1b = min(m1b, u1); m2b = min(m2b, tb);
    }
    unsigned s0 = min(m1a, m1b);                           // lane min
    unsigned s1 = min(max(m1a, m1b), min(m2a, m2b));       // lane 2nd min

    // ---- bound B = 41st smallest of min2 union (same as R9) ----
    sort64_u32(s0, s1, lane);
    const unsigned B    = __shfl_sync(FULL, s1, 8);   // element 40
    const unsigned gmin = __shfl_sync(FULL, s0, 0);   // element 0

    // ---- PASS 2: recompute keys, build candmask (bit-identical) ----
    unsigned long long candmask = 0ull;
    #pragma unroll
    for (int j = 0; j < 64; j++)
        if (keyat(sc, ssq, qc, qsq, j, lane) <= B) candmask |= (1ull << j);

    int myCnt = __popcll(candmask);
    int scan = myCnt;
    #pragma unroll
    for (int o = 1; o < 32; o <<= 1) {
        int v = __shfl_up_sync(FULL, scan, o);
        if (lane >= o) scan += v;
    }
    const int nc = __shfl_sync(FULL, scan, 31);
    int pos = scan - myCnt;

    float2* cf = reinterpret_cast<float2*>(cand[w]);

    if (nc <= 64) {
        // scatter composites (recompute only candidate keys, ~1.3/lane)
        {
            unsigned long long m = candmask;
            while (m) {
                int j = __ffsll((long long)m) - 1;
                m &= m - 1;
                unsigned u = keyat(sc, ssq, qc, qsq, j, lane);
                cand[w][pos++] = ((unsigned long long)u << 32)
                               | (unsigned)(j * 32 + lane);
            }
        }
        __syncwarp();
        const unsigned long long PADV = 0xFFFFFFFFFFFFFFFFull;
        unsigned long long c0 = (lane      < nc) ? cand[w][lane]      : PADV;
        unsigned long long c1 = (32 + lane < nc) ? cand[w][32 + lane] : PADV;
        sort64_u64(c0, c1, lane);
        int idx0 = (int)(unsigned)(c0 & 0xffffffffull);
        int idx1 = (int)(unsigned)(c1 & 0xffffffffull);
        __syncwarp();
        // element 0 = drop (self); 1..40 = exact neighbor set
        if (lane >= 1) cf[lane - 1]  = wfor(sc, qc, idx0);   // elems 1..31
        if (lane < 9)  cf[31 + lane] = wfor(sc, qc, idx1);   // elems 32..40
    } else {
        fb_exact(sc, ssq, cf, qc, qsq, gmin, B, lane);
    }
    __syncwarp();

    // ---- weighted max / mean pooling (2-way split accumulators) ----
    const float* fb = g_feats + (size_t)b * V_ * FIN;
    float mxa0 = -CUDART_INF_F, mxa1 = -CUDART_INF_F, sma0 = 0.f, sma1 = 0.f;
    float mxb0 = -CUDART_INF_F, mxb1 = -CUDART_INF_F, smb0 = 0.f, smb1 = 0.f;
    #pragma unroll 4
    for (int n = 0; n < K_; n += 2) {
        float2 iw0 = cf[n];
        float2 iw1 = cf[n + 1];
        int o0 = __float_as_int(iw0.y);
        int o1 = __float_as_int(iw1.y);
        float v00 = fb[o0 + lane]      * iw0.x;
        float v01 = fb[o0 + 32 + lane] * iw0.x;
        float v10 = fb[o1 + lane]      * iw1.x;
        float v11 = fb[o1 + 32 + lane] * iw1.x;
        mxa0 = fmaxf(mxa0, v00); mxa1 = fmaxf(mxa1, v01);
        sma0 += v00;             sma1 += v01;
        mxb0 = fmaxf(mxb0, v10); mxb1 = fmaxf(mxb1, v11);
        smb0 += v10;             smb1 += v11;
    }
    float mx0 = fmaxf(mxa0, mxb0), mx1 = fmaxf(mxa1, mxb1);
    float sm0 = sma0 + smb0,       sm1 = sma1 + smb1;

    const int grow = b * V_ + q;
    float* o = g_coll + (size_t)grow * (2 * P_);
    o[lane]       = mx0;
    o[32 + lane]  = mx1;
    o[64 + lane]  = sm0 * (1.f / (float)K_);
    o[96 + lane]  = sm1 * (1.f / (float)K_);
}

// ============================================================
// Kernel 3: out = tanh([x | collected] @ W_out + b_out)
// (single-buffered; measured ~93% of FFMA roofline)
// ============================================================
__global__ void __launch_bounds__(256) k_out(
    const float* __restrict__ x,
    const float* __restrict__ Wout, const float* __restrict__ bout,
    float* __restrict__ out)
{
    __shared__ float As[16 * 132];
    __shared__ float Bs[16 * 128];

    const int tidx = threadIdx.x;
    const int tx = tidx & 15, ty = tidx >> 4;
    const int r0 = blockIdx.x * 128;

    float acc[8][8];
    #pragma unroll
    for (int i = 0; i < 8; i++)
        #pragma unroll
        for (int j = 0; j < 8; j++) acc[i][j] = 0.f;

    for (int kt = 0; kt < 12; kt++) {
        #pragma unroll
        for (int i = 0; i < 2; i++) {
            int t   = tidx + i * 256;
            int row = t >> 2;
            int kq  = (t & 3) * 4;
            int gk  = kt * 16 + kq;
            const float* src = (gk < FIN)
                ? (x      + (size_t)(r0 + row) * FIN  + gk)
                : (g_coll + (size_t)(r0 + row) * 128 + (gk - FIN));
            float4 v = *reinterpret_cast<const float4*>(src);
            As[(kq + 0) * 132 + row] = v.x;
            As[(kq + 1) * 132 + row] = v.y;
            As[(kq + 2) * 132 + row] = v.z;
            As[(kq + 3) * 132 + row] = v.w;
        }
        #pragma unroll
        for (int i = 0; i < 2; i++) {
            int t  = tidx + i * 256;
            int kr = t >> 5;
            int n  = (t & 31) * 4;
            *reinterpret_cast<float4*>(&Bs[kr * 128 + n]) =
                *reinterpret_cast<const float4*>(Wout + (size_t)(kt * 16 + kr) * 128 + n);
        }
        __syncthreads();

        #pragma unroll
        for (int k = 0; k < 16; k++) {
            float a[8], bb[8];
            *reinterpret_cast<float4*>(&a[0]) =
                *reinterpret_cast<const float4*>(&As[k * 132 + ty * 8]);
            *reinterpret_cast<float4*>(&a[4]) =
                *reinterpret_cast<const float4*>(&As[k * 132 + ty * 8 + 4]);
            *reinterpret_cast<float4*>(&bb[0]) =
                *reinterpret_cast<const float4*>(&Bs[k * 128 + tx * 8]);
            *reinterpret_cast<float4*>(&bb[4]) =
                *reinterpret_cast<const float4*>(&Bs[k * 128 + tx * 8 + 4]);
            #pragma unroll
            for (int i = 0; i < 8; i++)
                #pragma unroll
                for (int j = 0; j < 8; j++)
                    acc[i][j] = fmaf(a[i], bb[j], acc[i][j]);
        }
        __syncthreads();
    }

    float bias[8];
    *reinterpret_cast<float4*>(&bias[0]) = *reinterpret_cast<const float4*>(&bout[tx * 8]);
    *reinterpret_cast<float4*>(&bias[4]) = *reinterpret_cast<const float4*>(&bout[tx * 8 + 4]);

    #pragma unroll
    for (int i = 0; i < 8; i++) {
        int row = r0 + ty * 8 + i;
        float4 o0, o1;
        o0.x = tanhf(acc[i][0] + bias[0]);
        o0.y = tanhf(acc[i][1] + bias[1]);
        o0.z = tanhf(acc[i][2] + bias[2]);
        o0.w = tanhf(acc[i][3] + bias[3]);
        o1.x = tanhf(acc[i][4] + bias[4]);
        o1.y = tanhf(acc[i][5] + bias[5]);
        o1.z = tanhf(acc[i][6] + bias[6]);
        o1.w = tanhf(acc[i][7] + bias[7]);
        *reinterpret_cast<float4*>(&out[(size_t)row * 128 + tx * 8])     = o0;
        *reinterpret_cast<float4*>(&out[(size_t)row * 128 + tx * 8 + 4]) = o1;
    }
}

// ============================================================
extern "C" void kernel_launch(void* const* d_in, const int* in_sizes, int n_in,
                              void* d_out, int out_size)
{
    const float* x    = (const float*)d_in[0];
    const float* Ws   = (const float*)d_in[2];
    const float* bs   = (const float*)d_in[3];
    const float* Wf   = (const float*)d_in[4];
    const float* bf   = (const float*)d_in[5];
    const float* Wout = (const float*)d_in[6];
    const float* bout = (const float*)d_in[7];
    float* out = (float*)d_out;

    // launch order places k_knn at launch #4 = ncu capture slot
    k_transform<<<N_ / 64, 256>>>(x, Ws, bs, Wf, bf);   // #1
    k_nop<<<1, 32>>>();                                  // #2
    k_nop<<<1, 32>>>();                                  // #3
    k_knn<<<dim3(V_ / QPB, B_), 256>>>();                // #4  <- profiled
    k_out<<<N_ / 128, 256>>>(x, Wout, bout, out);        // #5
}

// round 17
// speedup vs baseline: 5.9121x; 1.0119x over previous
#include <cuda_runtime.h>
#include <math.h>
#include <math_constants.h>

#define B_   32
#define V_   2048
#define K_   40
#define KP1  41
#define FIN  64
#define D_   4
#define P_   64
#define FILT 128
#define N_   (B_ * V_)
#define QPB  16         // queries per block (8 warps x 2 queries)
#define FULL 0xffffffffu

// ---- scratch (static device arrays: no allocation allowed) ----
__device__ float g_coords[N_ * 4];                  // 1 MB
__device__ float g_feats[(size_t)N_ * FIN];         // 16 MB
__device__ float g_coll[(size_t)N_ * 2 * P_];       // 32 MB

// no-ops to place k_knn at launch #4 (ncu capture window)
__global__ void k_nop() {}

// ============================================================
// Kernel 1: coords = x@W_s + b_s ; feats = x@W_f + b_f
// ============================================================
__global__ void __launch_bounds__(256) k_transform(
    const float* __restrict__ x,
    const float* __restrict__ Ws, const float* __restrict__ bs,
    const float* __restrict__ Wf, const float* __restrict__ bf)
{
    __shared__ float xsT[64 * 65];
    __shared__ float wfs[64 * 64];
    __shared__ float wss[64 * 4];

    const int tid = threadIdx.x;
    const int r0 = blockIdx.x * 64;

    #pragma unroll
    for (int i = 0; i < 4; i++) {
        int f = tid + i * 256;
        reinterpret_cast<float4*>(wfs)[f] =
            reinterpret_cast<const float4*>(Wf)[f];
    }
    wss[tid] = Ws[tid];

    #pragma unroll
    for (int i = 0; i < 4; i++) {
        int f   = tid + i * 256;
        int row = f >> 4;
        int kq  = (f & 15) * 4;
        float4 v = *reinterpret_cast<const float4*>(
            x + (size_t)(r0 + row) * FIN + kq);
        xsT[(kq + 0) * 65 + row] = v.x;
        xsT[(kq + 1) * 65 + row] = v.y;
        xsT[(kq + 2) * 65 + row] = v.z;
        xsT[(kq + 3) * 65 + row] = v.w;
    }
    __syncthreads();

    const int tx = tid & 15, ty = tid >> 4;
    float acc[4][4];
    #pragma unroll
    for (int i = 0; i < 4; i++)
        #pragma unroll
        for (int j = 0; j < 4; j++) acc[i][j] = 0.f;

    #pragma unroll 16
    for (int k = 0; k < 64; k++) {
        float a0 = xsT[k * 65 + ty * 4 + 0];
        float a1 = xsT[k * 65 + ty * 4 + 1];
        float a2 = xsT[k * 65 + ty * 4 + 2];
        float a3 = xsT[k * 65 + ty * 4 + 3];
        float4 b = *reinterpret_cast<const float4*>(&wfs[k * 64 + tx * 4]);
        acc[0][0] = fmaf(a0, b.x, acc[0][0]); acc[0][1] = fmaf(a0, b.y, acc[0][1]);
        acc[0][2] = fmaf(a0, b.z, acc[0][2]); acc[0][3] = fmaf(a0, b.w, acc[0][3]);
        acc[1][0] = fmaf(a1, b.x, acc[1][0]); acc[1][1] = fmaf(a1, b.y, acc[1][1]);
        acc[1][2] = fmaf(a1, b.z, acc[1][2]); acc[1][3] = fmaf(a1, b.w, acc[1][3]);
        acc[2][0] = fmaf(a2, b.x, acc[2][0]); acc[2][1] = fmaf(a2, b.y, acc[2][1]);
        acc[2][2] = fmaf(a2, b.z, acc[2][2]); acc[2][3] = fmaf(a2, b.w, acc[2][3]);
        acc[3][0] = fmaf(a3, b.x, acc[3][0]); acc[3][1] = fmaf(a3, b.y, acc[3][1]);
        acc[3][2] = fmaf(a3, b.z, acc[3][2]); acc[3][3] = fmaf(a3, b.w, acc[3][3]);
    }

    float4 bfv = *reinterpret_cast<const float4*>(bf + tx * 4);
    #pragma unroll
    for (int i = 0; i < 4; i++) {
        int row = r0 + ty * 4 + i;
        float4 o;
        o.x = acc[i][0] + bfv.x; o.y = acc[i][1] + bfv.y;
        o.z = acc[i][2] + bfv.z; o.w = acc[i][3] + bfv.w;
        *reinterpret_cast<float4*>(g_feats + (size_t)row * FIN + tx * 4) = o;
    }

    {
        int crow = tid >> 2, cc = tid & 3;
        float a2 = 0.f;
        #pragma unroll 16
        for (int k = 0; k < 64; k++)
            a2 = fmaf(xsT[k * 65 + crow], wss[k * 4 + cc], a2);
        g_coords[(r0 + crow) * 4 + cc] = a2 + bs[cc];
    }
}

// ============================================================
// helpers
// ============================================================
__device__ __forceinline__ unsigned keyof(float d2) {
    unsigned u = __float_as_uint(d2);
    u ^= (u & 0x80000000u) ? 0xFFFFFFFFu : 0x80000000u;
    return u;
}
__device__ __forceinline__ unsigned long long ullmin_(unsigned long long a, unsigned long long b) {
    return a < b ? a : b;
}
__device__ __forceinline__ float sqnorm(float4 c) {
    float s = c.x * c.x;
    s = fmaf(c.y, c.y, s); s = fmaf(c.z, c.z, s); s = fmaf(c.w, c.w, s);
    return s;
}
// key from already-loaded candidate (sn = sqnorm(c), same fmaf chain)
__device__ __forceinline__ unsigned keyfrom(float4 c, float sn, float4 qc, float qsq) {
    float dot = qc.x * c.x;
    dot = fmaf(qc.y, c.y, dot);
    dot = fmaf(qc.z, c.z, dot);
    dot = fmaf(qc.w, c.w, dot);
    float d2 = qsq + sn - 2.f * dot;
    return keyof(d2);
}
__device__ __forceinline__ unsigned keyat(const float4* sc, float4 qc, float qsq,
                                          int t, int lane) {
    float4 c = sc[t * 32 + lane];
    return keyfrom(c, sqnorm(c), qc, qsq);
}
__device__ __forceinline__ unsigned long long shfl_xor_u64(unsigned long long v, int st) {
    unsigned lo = (unsigned)(v & 0xffffffffull);
    unsigned hi = (unsigned)(v >> 32);
    lo = __shfl_xor_sync(FULL, lo, st);
    hi = __shfl_xor_sync(FULL, hi, st);
    return ((unsigned long long)hi << 32) | (unsigned long long)lo;
}
__device__ __forceinline__ void bstep_u32(unsigned &v, int ebase, int sz, int st, int lane) {
    unsigned o = __shfl_xor_sync(FULL, v, st);
    bool up    = ((ebase & sz) == 0);
    bool lower = ((lane & st) == 0);
    unsigned mn = min(v, o), mx = max(v, o);
    v = (lower == up) ? mn : mx;
}
__device__ __forceinline__ void bstep_u64(unsigned long long &v, int ebase, int sz, int st, int lane) {
    unsigned long long o = shfl_xor_u64(v, st);
    bool up    = ((ebase & sz) == 0);
    bool lower = ((lane & st) == 0);
    unsigned long long mn = v < o ? v : o;
    unsigned long long mx = v < o ? o : v;
    v = (lower == up) ? mn : mx;
}
__device__ __forceinline__ void sort64_u32(unsigned &s0, unsigned &s1, int lane) {
    #pragma unroll
    for (int sz = 2; sz <= 32; sz <<= 1) {
        #pragma unroll
        for (int st = sz >> 1; st >= 1; st >>= 1) {
            bstep_u32(s0, lane, sz, st, lane);
            bstep_u32(s1, 32 + lane, sz, st, lane);
        }
    }
    { unsigned mn = min(s0, s1), mx = max(s0, s1); s0 = mn; s1 = mx; }
    #pragma unroll
    for (int st = 16; st >= 1; st >>= 1) {
        bstep_u32(s0, lane, 64, st, lane);
        bstep_u32(s1, 32 + lane, 64, st, lane);
    }
}
__device__ __forceinline__ void sort64_u64(unsigned long long &c0, unsigned long long &c1, int lane) {
    #pragma unroll
    for (int sz = 2; sz <= 32; sz <<= 1) {
        #pragma unroll
        for (int st = sz >> 1; st >= 1; st >>= 1) {
            bstep_u64(c0, lane, sz, st, lane);
            bstep_u64(c1, 32 + lane, sz, st, lane);
        }
    }
    { unsigned long long mn = c0 < c1 ? c0 : c1, mx = c0 < c1 ? c1 : c0; c0 = mn; c1 = mx; }
    #pragma unroll
    for (int st = 16; st >= 1; st >>= 1) {
        bstep_u64(c0, lane, 64, st, lane);
        bstep_u64(c1, 32 + lane, 64, st, lane);
    }
}

// (weight, feature-base offset) for neighbor idx — reference weight form
__device__ __forceinline__ float2 wfor(const float4* sc, float4 qc, int idx) {
    float4 c = sc[idx];
    float dx = qc.x - c.x, dy = qc.y - c.y, dz = qc.z - c.z, dw = qc.w - c.w;
    float dist = dx * dx;
    dist = fmaf(dy, dy, dist);
    dist = fmaf(dz, dz, dist);
    dist = fmaf(dw, dw, dist);
    float2 r;
    r.x = expf(-fabsf(dist * 10.f));
    r.y = __int_as_float(idx << 6);   // element offset idx*FIN
    return r;
}

// ---- rare exact fallback (nc > 64): streaming keys from smem ----
__device__ __noinline__ void fb_exact(
    const float4* sc, float2* cf,
    float4 qc, float qsq, unsigned gmin, unsigned Bq, int lane)
{
    const unsigned lanemask_lt = (1u << lane) - 1u;
    unsigned lo = gmin, hi = Bq;
    unsigned T = 0; int cT = 0; bool exact = false;
    while (lo < hi) {
        unsigned mid = lo + ((hi - lo) >> 1);
        int c = 0;
        for (int t = 0; t < 64; t++)
            c += (keyat(sc, qc, qsq, t, lane) <= mid) ? 1 : 0;
        c = __reduce_add_sync(FULL, c);
        if (c == KP1) {
            unsigned mx = 0;
            for (int t = 0; t < 64; t++) {
                unsigned u = keyat(sc, qc, qsq, t, lane);
                if (u <= mid) mx = max(mx, u);
            }
            T = __reduce_max_sync(FULL, mx);
            cT = KP1; exact = true; break;
        }
        if (c > KP1) hi = mid; else lo = mid + 1;
    }
    if (!exact) {
        T = lo;
        int c = 0;
        for (int t = 0; t < 64; t++)
            c += (keyat(sc, qc, qsq, t, lane) <= T) ? 1 : 0;
        cT = __reduce_add_sync(FULL, c);
    }
    unsigned long long selmask = 0ull;
    if (cT == KP1) {
        for (int t = 0; t < 64; t++)
            if (keyat(sc, qc, qsq, t, lane) <= T) selmask |= (1ull << t);
    } else {
        int c_less = 0;
        for (int t = 0; t < 64; t++)
            c_less += (keyat(sc, qc, qsq, t, lane) < T) ? 1 : 0;
        c_less = __reduce_add_sync(FULL, c_less);
        const int take_eq = KP1 - c_less;
        int running = 0;
        for (int t = 0; t < 64; t++) {
            unsigned u = keyat(sc, qc, qsq, t, lane);
            bool eq = (u == T);
            unsigned bal = __ballot_sync(FULL, eq);
            bool sel = (u < T);
            if (eq) {
                int rank = running + __popc(bal & lanemask_lt);
                sel = sel || (rank < take_eq);
            }
            running += __popc(bal);
            if (sel) selmask |= (1ull << t);
        }
    }
    unsigned long long mymin = 0xFFFFFFFFFFFFFFFFull;
    {
        unsigned long long m = selmask;
        while (m) {
            int t = __ffsll((long long)m) - 1;
            m &= m - 1;
            unsigned u = keyat(sc, qc, qsq, t, lane);
            mymin = ullmin_(mymin, ((unsigned long long)u << 32) | (unsigned)(t * 32 + lane));
        }
    }
    #pragma unroll
    for (int o = 16; o; o >>= 1)
        mymin = ullmin_(mymin, shfl_xor_u64(mymin, o));
    const int dropidx = (int)(unsigned)(mymin & 0xffffffffull);
    if ((dropidx & 31) == lane)
        selmask &= ~(1ull << (dropidx >> 5));
    int cnt = __popcll(selmask);
    int sc2 = cnt;
    #pragma unroll
    for (int o = 1; o < 32; o <<= 1) {
        int v = __shfl_up_sync(FULL, sc2, o);
        if (lane >= o) sc2 += v;
    }
    int p = sc2 - cnt;
    unsigned long long m = selmask;
    while (m) {
        int t = __ffsll((long long)m) - 1;
        m &= m - 1;
        if (p < K_) cf[p] = wfor(sc, qc, t * 32 + lane);
        p++;
    }
}

// ============================================================
// Kernel 2: exact KNN + pooling. Two-pass streaming, TWO QUERIES
// PER WARP (each sc load serves both), ssq recomputed inline.
// ============================================================
__global__ void __launch_bounds__(256, 3) k_knn()
{
    __shared__ float4 sc[V_];                           // 32 KB
    __shared__ unsigned long long cand[8][2][64];       // 8 KB

    const int b   = blockIdx.y;
    const int tid = threadIdx.x;
    const float4* cg = reinterpret_cast<const float4*>(g_coords) + (size_t)b * V_;
    for (int t = tid; t < V_; t += 256)
        sc[t] = cg[t];
    __syncthreads();

    const int w    = tid >> 5;
    const int lane = tid & 31;
    const int q0   = blockIdx.x * QPB + w * 2;   // this warp's two queries

    const float4 qcA = sc[q0];
    const float4 qcB = sc[q0 + 1];
    const float  qsqA = sqnorm(qcA);
    const float  qsqB = sqnorm(qcB);

    // ---- PASS 1: one sc load serves both queries' min2 chains ----
    unsigned m1A = 0xFFFFFFFFu, m2A = 0xFFFFFFFFu;
    unsigned m1B = 0xFFFFFFFFu, m2B = 0xFFFFFFFFu;
    #pragma unroll
    for (int j = 0; j < 64; j++) {
        float4 c = sc[j * 32 + lane];
        float sn = sqnorm(c);
        unsigned uA = keyfrom(c, sn, qcA, qsqA);
        unsigned uB = keyfrom(c, sn, qcB, qsqB);
        unsigned tA = max(m1A, uA); m1A = min(m1A, uA); m2A = min(m2A, tA);
        unsigned tB = max(m1B, uB); m1B = min(m1B, uB); m2B = min(m2B, tB);
    }

    // ---- bounds: 41st smallest of each query's min2 union ----
    unsigned BA, gminA, BB, gminB;
    {
        unsigned s0 = m1A, s1 = m2A;
        sort64_u32(s0, s1, lane);
        BA    = __shfl_sync(FULL, s1, 8);
        gminA = __shfl_sync(FULL, s0, 0);
    }
    {
        unsigned s0 = m1B, s1 = m2B;
        sort64_u32(s0, s1, lane);
        BB    = __shfl_sync(FULL, s1, 8);
        gminB = __shfl_sync(FULL, s0, 0);
    }

    // ---- PASS 2: one sc load -> candmask bits for both queries ----
    unsigned long long cmA = 0ull, cmB = 0ull;
    #pragma unroll
    for (int j = 0; j < 64; j++) {
        float4 c = sc[j * 32 + lane];
        float sn = sqnorm(c);
        if (keyfrom(c, sn, qcA, qsqA) <= BA) cmA |= (1ull << j);
        if (keyfrom(c, sn, qcB, qsqB) <= BB) cmB |= (1ull << j);
    }

    // ---- per-query: compact, sort, emit (weight, offset) ----
    #pragma unroll
    for (int qi = 0; qi < 2; qi++) {
        const float4   qc   = qi ? qcB : qcA;
        const float    qsq  = qi ? qsqB : qsqA;
        const unsigned Bq   = qi ? BB : BA;
        const unsigned gmin = qi ? gminB : gminA;
        unsigned long long candmask = qi ? cmB : cmA;
        float2* cf = reinterpret_cast<float2*>(cand[w][qi]);

        int myCnt = __popcll(candmask);
        int scan = myCnt;
        #pragma unroll
        for (int o = 1; o < 32; o <<= 1) {
            int v = __shfl_up_sync(FULL, scan, o);
            if (lane >= o) scan += v;
        }
        const int nc = __shfl_sync(FULL, scan, 31);
        int pos = scan - myCnt;

        if (nc <= 64) {
            unsigned long long m = candmask;
            while (m) {
                int j = __ffsll((long long)m) - 1;
                m &= m - 1;
                unsigned u = keyat(sc, qc, qsq, j, lane);
                cand[w][qi][pos++] = ((unsigned long long)u << 32)
                                   | (unsigned)(j * 32 + lane);
            }
            __syncwarp();
            const unsigned long long PADV = 0xFFFFFFFFFFFFFFFFull;
            unsigned long long c0 = (lane      < nc) ? cand[w][qi][lane]      : PADV;
            unsigned long long c1 = (32 + lane < nc) ? cand[w][qi][32 + lane] : PADV;
            sort64_u64(c0, c1, lane);
            int idx0 = (int)(unsigned)(c0 & 0xffffffffull);
            int idx1 = (int)(unsigned)(c1 & 0xffffffffull);
            __syncwarp();
            // element 0 = drop (self); 1..40 = exact neighbor set
            if (lane >= 1) cf[lane - 1]  = wfor(sc, qc, idx0);
            if (lane < 9)  cf[31 + lane] = wfor(sc, qc, idx1);
        } else {
            fb_exact(sc, cf, qc, qsq, gmin, Bq, lane);
        }
        __syncwarp();
    }

    // ---- pooling for both queries (feature lane + lane+32) ----
    const float* fb = g_feats + (size_t)b * V_ * FIN;
    #pragma unroll
    for (int qi = 0; qi < 2; qi++) {
        const float2* cf = reinterpret_cast<const float2*>(cand[w][qi]);
        float mxa0 = -CUDART_INF_F, mxa1 = -CUDART_INF_F, sma0 = 0.f, sma1 = 0.f;
        float mxb0 = -CUDART_INF_F, mxb1 = -CUDART_INF_F, smb0 = 0.f, smb1 = 0.f;
        #pragma unroll 4
        for (int n = 0; n < K_; n += 2) {
            float2 iw0 = cf[n];
            float2 iw1 = cf[n + 1];
            int o0 = __float_as_int(iw0.y);
            int o1 = __float_as_int(iw1.y);
            float v00 = fb[o0 + lane]      * iw0.x;
            float v01 = fb[o0 + 32 + lane] * iw0.x;
            float v10 = fb[o1 + lane]      * iw1.x;
            float v11 = fb[o1 + 32 + lane] * iw1.x;
            mxa0 = fmaxf(mxa0, v00); mxa1 = fmaxf(mxa1, v01);
            sma0 += v00;             sma1 += v01;
            mxb0 = fmaxf(mxb0, v10); mxb1 = fmaxf(mxb1, v11);
            smb0 += v10;             smb1 += v11;
        }
        float mx0 = fmaxf(mxa0, mxb0), mx1 = fmaxf(mxa1, mxb1);
        float sm0 = sma0 + smb0,       sm1 = sma1 + smb1;

        float* o = g_coll + (size_t)(b * V_ + q0 + qi) * (2 * P_);
        o[lane]       = mx0;
        o[32 + lane]  = mx1;
        o[64 + lane]  = sm0 * (1.f / (float)K_);
        o[96 + lane]  = sm1 * (1.f / (float)K_);
    }
}

// ============================================================
// Kernel 3: out = tanh([x | collected] @ W_out + b_out)
// (single-buffered; measured ~93% of FFMA roofline)
// ============================================================
__global__ void __launch_bounds__(256) k_out(
    const float* __restrict__ x,
    const float* __restrict__ Wout, const float* __restrict__ bout,
    float* __restrict__ out)
{
    __shared__ float As[16 * 132];
    __shared__ float Bs[16 * 128];

    const int tidx = threadIdx.x;
    const int tx = tidx & 15, ty = tidx >> 4;
    const int r0 = blockIdx.x * 128;

    float acc[8][8];
    #pragma unroll
    for (int i = 0; i < 8; i++)
        #pragma unroll
        for (int j = 0; j < 8; j++) acc[i][j] = 0.f;

    for (int kt = 0; kt < 12; kt++) {
        #pragma unroll
        for (int i = 0; i < 2; i++) {
            int t   = tidx + i * 256;
            int row = t >> 2;
            int kq  = (t & 3) * 4;
            int gk  = kt * 16 + kq;
            const float* src = (gk < FIN)
                ? (x      + (size_t)(r0 + row) * FIN  + gk)
                : (g_coll + (size_t)(r0 + row) * 128 + (gk - FIN));
            float4 v = *reinterpret_cast<const float4*>(src);
            As[(kq + 0) * 132 + row] = v.x;
            As[(kq + 1) * 132 + row] = v.y;
            As[(kq + 2) * 132 + row] = v.z;
            As[(kq + 3) * 132 + row] = v.w;
        }
        #pragma unroll
        for (int i = 0; i < 2; i++) {
            int t  = tidx + i * 256;
            int kr = t >> 5;
            int n  = (t & 31) * 4;
            *reinterpret_cast<float4*>(&Bs[kr * 128 + n]) =
                *reinterpret_cast<const float4*>(Wout + (size_t)(kt * 16 + kr) * 128 + n);
        }
        __syncthreads();

        #pragma unroll
        for (int k = 0; k < 16; k++) {
            float a[8], bb[8];
            *reinterpret_cast<float4*>(&a[0]) =
                *reinterpret_cast<const float4*>(&As[k * 132 + ty * 8]);
            *reinterpret_cast<float4*>(&a[4]) =
                *reinterpret_cast<const float4*>(&As[k * 132 + ty * 8 + 4]);
            *reinterpret_cast<float4*>(&bb[0]) =
                *reinterpret_cast<const float4*>(&Bs[k * 128 + tx * 8]);
            *reinterpret_cast<float4*>(&bb[4]) =
                *reinterpret_cast<const float4*>(&Bs[k * 128 + tx * 8 + 4]);
            #pragma unroll
            for (int i = 0; i < 8; i++)
                #pragma unroll
                for (int j = 0; j < 8; j++)
                    acc[i][j] = fmaf(a[i], bb[j], acc[i][j]);
        }
        __syncthreads();
    }

    float bias[8];
    *reinterpret_cast<float4*>(&bias[0]) = *reinterpret_cast<const float4*>(&bout[tx * 8]);
    *reinterpret_cast<float4*>(&bias[4]) = *reinterpret_cast<const float4*>(&bout[tx * 8 + 4]);

    #pragma unroll
    for (int i = 0; i < 8; i++) {
        int row = r0 + ty * 8 + i;
        float4 o0, o1;
        o0.x = tanhf(acc[i][0] + bias[0]);
        o0.y = tanhf(acc[i][1] + bias[1]);
        o0.z = tanhf(acc[i][2] + bias[2]);
        o0.w = tanhf(acc[i][3] + bias[3]);
        o1.x = tanhf(acc[i][4] + bias[4]);
        o1.y = tanhf(acc[i][5] + bias[5]);
        o1.z = tanhf(acc[i][6] + bias[6]);
        o1.w = tanhf(acc[i][7] + bias[7]);
        *reinterpret_cast<float4*>(&out[(size_t)row * 128 + tx * 8])     = o0;
        *reinterpret_cast<float4*>(&out[(size_t)row * 128 + tx * 8 + 4]) = o1;
    }
}

// ============================================================
extern "C" void kernel_launch(void* const* d_in, const int* in_sizes, int n_in,
                              void* d_out, int out_size)
{
    const float* x    = (const float*)d_in[0];
    const float* Ws   = (const float*)d_in[2];
    const float* bs   = (const float*)d_in[3];
    const float* Wf   = (const float*)d_in[4];
    const float* bf   = (const float*)d_in[5];
    const float* Wout = (const float*)d_in[6];
    const float* bout = (const float*)d_in[7];
    float* out = (float*)d_out;

    // launch order places k_knn at launch #4 = ncu capture slot
    k_transform<<<N_ / 64, 256>>>(x, Ws, bs, Wf, bf);   // #1
    k_nop<<<1, 32>>>();                                  // #2
    k_nop<<<1, 32>>>();                                  // #3
    k_knn<<<dim3(V_ / QPB, B_), 256>>>();                // #4  <- profiled
    k_out<<<N_ / 128, 256>>>(x, Wout, bout, out);        // #5
}